// round 5
// baseline (speedup 1.0000x reference)
#include <cuda_runtime.h>
#include <cuda_bf16.h>
#include <cstdint>
#include <math.h>

#define BB 4
#define SS 1024
#define DD 1024
#define NH 16
#define DKH 64
#define BHN (BB*NH)   // 64

typedef __nv_bfloat16 bf16;

// ---------------- device scratch ----------------
__device__ bf16  g_q[BB*NH*SS*DKH];                 // bf16 [b,h,s,dk], q pre-scaled 0.125
__device__ bf16  g_k[BB*NH*SS*DKH];
__device__ bf16  g_v[BB*NH*SS*DKH];
__device__ bf16  g_pb[(size_t)BHN*SS*SS];           // biased probs bf16, 128MB
__device__ bf16  g_pu[(size_t)BHN*64*SS];           // unbiased probs rows<64, 8MB
__device__ float g_ctx[BB*SS*DD];
__device__ float g_res[BB*SS*DD];

// ---------------- helpers ----------------
__device__ __forceinline__ float warpSumT(float v){
    #pragma unroll
    for (int o=16;o;o>>=1) v += __shfl_xor_sync(0xffffffffu, v, o);
    return v;
}
__device__ __forceinline__ float blockSum(float v, float* sh){
    v = warpSumT(v);
    int w = threadIdx.x >> 5, l = threadIdx.x & 31;
    if (l == 0) sh[w] = v;
    __syncthreads();
    float r = sh[0];
    #pragma unroll
    for (int i=1;i<8;i++) r += sh[i];
    __syncthreads();
    return r;
}
__device__ __forceinline__ void mma_tf32(float* d, const uint32_t* a, const uint32_t* b){
    asm volatile(
        "mma.sync.aligned.m16n8k8.row.col.f32.tf32.tf32.f32 "
        "{%0,%1,%2,%3}, {%4,%5,%6,%7}, {%8,%9}, {%0,%1,%2,%3};\n"
        : "+f"(d[0]), "+f"(d[1]), "+f"(d[2]), "+f"(d[3])
        : "r"(a[0]), "r"(a[1]), "r"(a[2]), "r"(a[3]),
          "r"(b[0]), "r"(b[1]));
}
__device__ __forceinline__ void mma_bf16(float* d, const uint32_t* a, const uint32_t* b){
    asm volatile(
        "mma.sync.aligned.m16n8k16.row.col.f32.bf16.bf16.f32 "
        "{%0,%1,%2,%3}, {%4,%5,%6,%7}, {%8,%9}, {%0,%1,%2,%3};\n"
        : "+f"(d[0]), "+f"(d[1]), "+f"(d[2]), "+f"(d[3])
        : "r"(a[0]), "r"(a[1]), "r"(a[2]), "r"(a[3]),
          "r"(b[0]), "r"(b[1]));
}
__device__ __forceinline__ void cpasync16(uint32_t s, const void* g){
    asm volatile("cp.async.cg.shared.global [%0], [%1], 16;\n" :: "r"(s), "l"(g));
}
__device__ __forceinline__ uint32_t smem_u32(const void* p){
    return (uint32_t)__cvta_generic_to_shared(p);
}
__device__ __forceinline__ uint32_t pack_bf16x2(float x, float y){
    __nv_bfloat162 a = __floats2bfloat162_rn(x, y);
    return *reinterpret_cast<uint32_t*>(&a);
}

// =====================================================================
// tf32 GEMM for projections (fp32 A,B).
//  MODE 0: QKV proj -> bf16 head-layout scatter, (acc+bias)*scale
//  MODE 2: out proj -> fp32, + bias + residual (flat)
// =====================================================================
template<int MODE>
__global__ void __launch_bounds__(128)
mma_gemm(const float* __restrict__ A, const float* __restrict__ Bg,
         const float* __restrict__ bias, const float* __restrict__ resid,
         void* __restrict__ Cv, int M, int N, int K, float scale)
{
    constexpr int BM=128, BN=128, BK=32, S=36;
    constexpr int T=128, MT=4, NTL=8;

    extern __shared__ float sm[];
    float* As = sm;
    float* Bs = sm + 2*BM*S;

    const int tid = threadIdx.x;
    const int bm0 = blockIdx.y*BM, bn0 = blockIdx.x*BN;

    auto loadA = [&](int buf, int k0){
        #pragma unroll
        for (int i = 0; i < 8; i++){
            int id = tid + i*T;
            int r = id >> 3, ks = (id & 7)*4;
            cpasync16(smem_u32(&As[buf*BM*S + r*S + ks]),
                      A + (size_t)(bm0 + r)*K + k0 + ks);
        }
    };
    auto loadB = [&](int buf, int k0){
        #pragma unroll
        for (int i = 0; i < 8; i++){
            int id = tid + i*T;
            int r = id >> 3, ks = (id & 7)*4;
            cpasync16(smem_u32(&Bs[buf*BN*S + r*S + ks]),
                      Bg + (size_t)(bn0 + r)*K + k0 + ks);
        }
    };

    const int lane = tid & 31, g = lane >> 2, tg = lane & 3;
    const int warp = tid >> 5;
    const int wm = (warp >> 1) * 64, wn = (warp & 1) * 64;

    float acc[MT][NTL][4];
    #pragma unroll
    for (int i=0;i<MT;i++)
        #pragma unroll
        for (int j=0;j<NTL;j++)
            #pragma unroll
            for (int r=0;r<4;r++) acc[i][j][r] = 0.f;

    const int nt = K / BK;
    loadA(0, 0); loadB(0, 0);
    asm volatile("cp.async.commit_group;\n");

    for (int it = 0; it < nt; it++){
        int buf = it & 1;
        if (it + 1 < nt) {
            loadA(buf^1, (it+1)*BK); loadB(buf^1, (it+1)*BK);
            asm volatile("cp.async.commit_group;\n");
            asm volatile("cp.async.wait_group 1;\n");
        } else {
            asm volatile("cp.async.wait_group 0;\n");
        }
        __syncthreads();

        const float* Ab = As + buf*BM*S;
        const float* Bb = Bs + buf*BN*S;
        #pragma unroll
        for (int c = 0; c < BK/8; c++){
            uint32_t af[MT][4], bf[NTL][2];
            #pragma unroll
            for (int i = 0; i < MT; i++){
                const float* ap = Ab + (wm + i*16 + g)*S + c*8 + tg;
                af[i][0] = __float_as_uint(ap[0]);
                af[i][1] = __float_as_uint(ap[8*S]);
                af[i][2] = __float_as_uint(ap[4]);
                af[i][3] = __float_as_uint(ap[8*S + 4]);
            }
            #pragma unroll
            for (int j = 0; j < NTL; j++){
                const float* bp = Bb + (wn + j*8 + g)*S + c*8 + tg;
                bf[j][0] = __float_as_uint(bp[0]);
                bf[j][1] = __float_as_uint(bp[4]);
            }
            #pragma unroll
            for (int i = 0; i < MT; i++)
                #pragma unroll
                for (int j = 0; j < NTL; j++)
                    mma_tf32(acc[i][j], af[i], bf[j]);
        }
        __syncthreads();
    }

    #pragma unroll
    for (int i = 0; i < MT; i++){
        #pragma unroll
        for (int rr = 0; rr < 2; rr++){
            int row = bm0 + wm + i*16 + g + rr*8;
            #pragma unroll
            for (int j = 0; j < NTL; j++){
                int col = bn0 + wn + j*8 + 2*tg;
                float vx = acc[i][j][rr*2 + 0];
                float vy = acc[i][j][rr*2 + 1];
                if (MODE == 0) {
                    vx = (vx + bias[col])   * scale;
                    vy = (vy + bias[col+1]) * scale;
                    int b = row >> 10, s = row & 1023;
                    int h = col >> 6, dd = col & 63;
                    bf16* C = (bf16*)Cv;
                    uint32_t u = pack_bf16x2(vx, vy);
                    *(uint32_t*)&C[((size_t)(b*NH + h) << 16) + s*DKH + dd] = u;
                } else {
                    float* C = (float*)Cv;
                    size_t idx = (size_t)row*N + col;
                    float2 r2 = *(const float2*)&resid[idx];
                    float2 o = make_float2(vx + bias[col] + r2.x,
                                           vy + bias[col+1] + r2.y);
                    *(float2*)&C[idx] = o;
                }
            }
        }
    }
}

// =====================================================================
// FUSED scores+softmax: per (qtile16, bh).  S[16,1024] in REGISTERS.
// Streams K; writes biased probs (bf16) and, for rows<64, unbiased probs.
// 256 threads = 8 warps; warp w owns cols [c*128 + w*16, +16) per chunk c.
// =====================================================================
#define KST 72   // K smem stride (bf16)
__global__ void __launch_bounds__(256, 2)
fused_scores_softmax(const bf16* __restrict__ Q, const bf16* __restrict__ K,
                     bf16* __restrict__ pb, bf16* __restrict__ pu,
                     const int* __restrict__ ts_ptr)
{
    __shared__ bf16 Qs[16*KST];
    __shared__ bf16 Ks[2][128*KST];
    __shared__ float mred[16][8];
    __shared__ float sred[16][8];

    const int tid  = threadIdx.x;
    const int lane = tid & 31, g = lane >> 2, tg = lane & 3;
    const int w    = tid >> 5;
    const int qt   = blockIdx.x;
    const int bh   = blockIdx.y;

    const bf16* Qb = Q + ((size_t)bh << 16) + (size_t)(qt*16)*DKH;
    const bf16* Kb = K + ((size_t)bh << 16);

    // load Q tile [16][64]
    if (tid < 128){
        int r = tid >> 3, c8 = (tid & 7) << 3;
        cpasync16(smem_u32(&Qs[r*KST + c8]), Qb + r*DKH + c8);
    }
    auto loadK = [&](int buf, int kr0){
        #pragma unroll
        for (int i = 0; i < 4; i++){
            int id = tid + (i << 8);
            int r = id >> 3, c8 = (id & 7) << 3;
            cpasync16(smem_u32(&Ks[buf][r*KST + c8]), Kb + (size_t)(kr0 + r)*DKH + c8);
        }
    };
    loadK(0, 0);
    asm volatile("cp.async.commit_group;\n");

    float acc[8][2][4];
    #pragma unroll
    for (int c=0;c<8;c++)
        #pragma unroll
        for (int j=0;j<2;j++)
            #pragma unroll
            for (int v=0;v<4;v++) acc[c][j][v]=0.f;

    uint32_t af[4][4];
    bool qloaded = false;

    for (int c = 0; c < 8; c++){
        int buf = c & 1;
        if (c + 1 < 8){
            loadK(buf^1, (c+1)*128);
            asm volatile("cp.async.commit_group;\n");
            asm volatile("cp.async.wait_group 1;\n");
        } else {
            asm volatile("cp.async.wait_group 0;\n");
        }
        __syncthreads();

        if (!qloaded){
            #pragma unroll
            for (int kk = 0; kk < 4; kk++){
                const bf16* ap = &Qs[g*KST + kk*16 + 2*tg];
                af[kk][0] = *(const uint32_t*)(ap);
                af[kk][1] = *(const uint32_t*)(ap + 8*KST);
                af[kk][2] = *(const uint32_t*)(ap + 8);
                af[kk][3] = *(const uint32_t*)(ap + 8*KST + 8);
            }
            qloaded = true;
        }

        #pragma unroll
        for (int kk = 0; kk < 4; kk++){
            #pragma unroll
            for (int j = 0; j < 2; j++){
                const bf16* bp = &Ks[buf][(w*16 + j*8 + g)*KST + kk*16 + 2*tg];
                uint32_t bfr[2];
                bfr[0] = *(const uint32_t*)(bp);
                bfr[1] = *(const uint32_t*)(bp + 8);
                mma_bf16(acc[c][j], af[kk], bfr);
            }
        }
        __syncthreads();
    }

    // ---------------- softmax phase ----------------
    const int grow0 = qt*16 + g;      // row for vals 0,1
    const int grow1 = grow0 + 8;      // row for vals 2,3
    const bool tsb = (ts_ptr[0] < 8);

    // bias values (only chunk 0, warps 0..3 touch cols<64)
    float bs[2][2][2] = {{{0.f,0.f},{0.f,0.f}},{{0.f,0.f},{0.f,0.f}}};
    if (qt < 4 && w < 4){
        #pragma unroll
        for (int j = 0; j < 2; j++){
            #pragma unroll
            for (int v = 0; v < 2; v++){
                int col = w*16 + j*8 + 2*tg + v;
                bs[0][j][v] = 0.1f / (fabsf((float)(grow0 - col)) + 1.0f);
                bs[1][j][v] = 0.1f / (fabsf((float)(grow1 - col)) + 1.0f);
            }
        }
    }

    auto softmax_store = [&](bool useBias, bf16* dstBase){
        // max pass
        float m0 = -1e30f, m1 = -1e30f;
        #pragma unroll
        for (int c = 0; c < 8; c++){
            #pragma unroll
            for (int j = 0; j < 2; j++){
                float b00 = (useBias && c==0) ? bs[0][j][0] : 0.f;
                float b01 = (useBias && c==0) ? bs[0][j][1] : 0.f;
                float b10 = (useBias && c==0) ? bs[1][j][0] : 0.f;
                float b11 = (useBias && c==0) ? bs[1][j][1] : 0.f;
                m0 = fmaxf(m0, fmaxf(acc[c][j][0]+b00, acc[c][j][1]+b01));
                m1 = fmaxf(m1, fmaxf(acc[c][j][2]+b10, acc[c][j][3]+b11));
            }
        }
        #pragma unroll
        for (int o=1;o<4;o<<=1){
            m0 = fmaxf(m0, __shfl_xor_sync(0xffffffffu, m0, o));
            m1 = fmaxf(m1, __shfl_xor_sync(0xffffffffu, m1, o));
        }
        __syncthreads();
        if (tg == 0){ mred[g][w] = m0; mred[g+8][w] = m1; }
        __syncthreads();
        float M0 = mred[g][0],  M1 = mred[g+8][0];
        #pragma unroll
        for (int i=1;i<8;i++){ M0 = fmaxf(M0, mred[g][i]); M1 = fmaxf(M1, mred[g+8][i]); }

        // sum pass
        float s0 = 0.f, s1 = 0.f;
        #pragma unroll
        for (int c = 0; c < 8; c++){
            #pragma unroll
            for (int j = 0; j < 2; j++){
                float b00 = (useBias && c==0) ? bs[0][j][0] : 0.f;
                float b01 = (useBias && c==0) ? bs[0][j][1] : 0.f;
                float b10 = (useBias && c==0) ? bs[1][j][0] : 0.f;
                float b11 = (useBias && c==0) ? bs[1][j][1] : 0.f;
                s0 += __expf(acc[c][j][0]+b00-M0) + __expf(acc[c][j][1]+b01-M0);
                s1 += __expf(acc[c][j][2]+b10-M1) + __expf(acc[c][j][3]+b11-M1);
            }
        }
        #pragma unroll
        for (int o=1;o<4;o<<=1){
            s0 += __shfl_xor_sync(0xffffffffu, s0, o);
            s1 += __shfl_xor_sync(0xffffffffu, s1, o);
        }
        __syncthreads();
        if (tg == 0){ sred[g][w] = s0; sred[g+8][w] = s1; }
        __syncthreads();
        float S0 = 0.f, S1 = 0.f;
        #pragma unroll
        for (int i=0;i<8;i++){ S0 += sred[g][i]; S1 += sred[g+8][i]; }
        float inv0 = 1.0f / S0, inv1 = 1.0f / S1;

        // store pass
        #pragma unroll
        for (int c = 0; c < 8; c++){
            #pragma unroll
            for (int j = 0; j < 2; j++){
                float b00 = (useBias && c==0) ? bs[0][j][0] : 0.f;
                float b01 = (useBias && c==0) ? bs[0][j][1] : 0.f;
                float b10 = (useBias && c==0) ? bs[1][j][0] : 0.f;
                float b11 = (useBias && c==0) ? bs[1][j][1] : 0.f;
                int col = c*128 + w*16 + j*8 + 2*tg;
                float e00 = __expf(acc[c][j][0]+b00-M0)*inv0;
                float e01 = __expf(acc[c][j][1]+b01-M0)*inv0;
                float e10 = __expf(acc[c][j][2]+b10-M1)*inv1;
                float e11 = __expf(acc[c][j][3]+b11-M1)*inv1;
                *(uint32_t*)&dstBase[((size_t)g      << 10) + col] = pack_bf16x2(e00, e01);
                *(uint32_t*)&dstBase[((size_t)(g+8)  << 10) + col] = pack_bf16x2(e10, e11);
            }
        }
    };

    bf16* pbrow = pb + ((size_t)bh << 20) + ((size_t)(qt*16) << 10);
    if (qt < 4){
        softmax_store(tsb, pbrow);
        bf16* purow = pu + ((size_t)(bh*64 + qt*16) << 10);
        softmax_store(false, purow);
    } else {
        softmax_store(false, pbrow);
    }
}

// ---------------- out2: head-mean of unbiased probs (fp32 accum) ------------
__global__ void __launch_bounds__(256)
out2_reduce(const bf16* __restrict__ pb, const bf16* __restrict__ pu,
            float* __restrict__ out2)
{
    const int b = blockIdx.y, row = blockIdx.x;
    const int tid = threadIdx.x;
    const int c0 = tid * 4;

    float4 acc = make_float4(0.f, 0.f, 0.f, 0.f);
    #pragma unroll 1
    for (int h = 0; h < NH; h++){
        const bf16* src = (row < 64)
            ? pu + ((((size_t)((b*NH + h)*64 + row))) << 10)
            : pb + (((size_t)(b*NH + h)) << 20) + (((size_t)row) << 10);
        uint2 u = *(const uint2*)(src + c0);
        __nv_bfloat162 lo = *reinterpret_cast<__nv_bfloat162*>(&u.x);
        __nv_bfloat162 hi = *reinterpret_cast<__nv_bfloat162*>(&u.y);
        acc.x += __bfloat162float(lo.x);  acc.y += __bfloat162float(lo.y);
        acc.z += __bfloat162float(hi.x);  acc.w += __bfloat162float(hi.y);
    }
    const float k = 1.0f / 16.0f;
    float4 o = make_float4(acc.x*k, acc.y*k, acc.z*k, acc.w*k);
    *(float4*)&out2[(((size_t)(b*SS + row)) << 10) + c0] = o;
}

// =====================================================================
// PV: ctx[b,s,h*64+n] = probs(bf16) @ V(bf16)
// =====================================================================
__global__ void __launch_bounds__(256)
pv_bf16(const bf16* __restrict__ P, const bf16* __restrict__ V,
        float* __restrict__ ctx)
{
    constexpr int BK = 32, SA = 40;
    __shared__ bf16 As[2][128*SA];
    __shared__ bf16 Vs[2][64*SA];

    const int bh = blockIdx.y;
    P   += (size_t)bh << 20;
    V   += (size_t)bh << 16;
    ctx += ((size_t)(bh >> 4) << 20) + (size_t)(bh & 15)*64;

    const int tid = threadIdx.x;
    const int lane = tid & 31, g = lane >> 2, tg = lane & 3;
    const int w = tid >> 5;
    const int wm = (w >> 1) * 32, wn = (w & 1) * 32;
    const int m0 = blockIdx.x * 128;

    auto loadA = [&](int buf, int k0){
        #pragma unroll
        for (int i = 0; i < 2; i++){
            int id = tid + i*256;
            int r = id >> 2, c8 = (id & 3) << 3;
            cpasync16(smem_u32(&As[buf][r*SA + c8]),
                      P + (((size_t)(m0 + r)) << 10) + k0 + c8);
        }
    };
    auto loadV = [&](int buf, int k0){
        int k  = tid & 31;
        int n8 = (tid >> 5) * 8;
        union { uint4 u; bf16 h[8]; } val;
        val.u = *(const uint4*)(V + (((size_t)(k0 + k)) << 6) + n8);
        #pragma unroll
        for (int t = 0; t < 8; t++)
            Vs[buf][(n8 + t)*SA + k] = val.h[t];
    };

    float acc[2][4][4];
    #pragma unroll
    for (int i=0;i<2;i++)
        #pragma unroll
        for (int j=0;j<4;j++)
            #pragma unroll
            for (int r=0;r<4;r++) acc[i][j][r]=0.f;

    loadA(0, 0);
    asm volatile("cp.async.commit_group;\n");
    loadV(0, 0);

    for (int it = 0; it < SS/BK; it++){
        int buf = it & 1;
        if (it + 1 < SS/BK){
            loadA(buf^1, (it+1)*BK);
            asm volatile("cp.async.commit_group;\n");
            loadV(buf^1, (it+1)*BK);
            asm volatile("cp.async.wait_group 1;\n");
        } else {
            asm volatile("cp.async.wait_group 0;\n");
        }
        __syncthreads();

        #pragma unroll
        for (int kk = 0; kk < 2; kk++){
            uint32_t af[2][4], bfr[4][2];
            #pragma unroll
            for (int i = 0; i < 2; i++){
                const bf16* ap = &As[buf][(wm + i*16 + g)*SA + kk*16 + 2*tg];
                af[i][0] = *(const uint32_t*)(ap);
                af[i][1] = *(const uint32_t*)(ap + 8*SA);
                af[i][2] = *(const uint32_t*)(ap + 8);
                af[i][3] = *(const uint32_t*)(ap + 8*SA + 8);
            }
            #pragma unroll
            for (int j = 0; j < 4; j++){
                const bf16* bp = &Vs[buf][(wn + j*8 + g)*SA + kk*16 + 2*tg];
                bfr[j][0] = *(const uint32_t*)(bp);
                bfr[j][1] = *(const uint32_t*)(bp + 8);
            }
            #pragma unroll
            for (int i = 0; i < 2; i++)
                #pragma unroll
                for (int j = 0; j < 4; j++)
                    mma_bf16(acc[i][j], af[i], bfr[j]);
        }
        __syncthreads();
    }

    #pragma unroll
    for (int i = 0; i < 2; i++){
        #pragma unroll
        for (int rr = 0; rr < 2; rr++){
            int row = m0 + wm + i*16 + g + rr*8;
            #pragma unroll
            for (int j = 0; j < 4; j++){
                int col = wn + j*8 + 2*tg;
                float2 o = make_float2(acc[i][j][rr*2+0], acc[i][j][rr*2+1]);
                *(float2*)&ctx[((size_t)row << 10) + col] = o;
            }
        }
    }
}

// ---------------- LayerNorm --------------------------------------------------
__global__ void __launch_bounds__(256)
layernorm(const float* __restrict__ R, const float* __restrict__ gamma,
          const float* __restrict__ beta, float* __restrict__ out)
{
    __shared__ float red[8];
    int row = blockIdx.x;
    int tid = threadIdx.x;
    const float* src = R + ((size_t)row << 10);
    float v[4];
    #pragma unroll
    for (int j=0;j<4;j++) v[j] = src[tid + (j<<8)];
    float s = v[0]+v[1]+v[2]+v[3];
    s = blockSum(s, red);
    float mu = s * (1.0f/1024.0f);
    float q = 0.f;
    #pragma unroll
    for (int j=0;j<4;j++) { float d = v[j]-mu; q += d*d; }
    q = blockSum(q, red);
    float inv = rsqrtf(q * (1.0f/1024.0f) + 1e-5f);
    #pragma unroll
    for (int j=0;j<4;j++) {
        int c = tid + (j<<8);
        out[((size_t)row << 10) + c] = (v[j]-mu)*inv*gamma[c] + beta[c];
    }
}

// ---------------- launch -----------------------------------------------------
extern "C" void kernel_launch(void* const* d_in, const int* in_sizes, int n_in,
                              void* d_out, int out_size)
{
    const float* x  = (const float*)d_in[0];
    const int*   ts = (const int*)  d_in[1];
    const float* Wq = (const float*)d_in[2];
    const float* bq = (const float*)d_in[3];
    const float* Wk = (const float*)d_in[4];
    const float* bk = (const float*)d_in[5];
    const float* Wv = (const float*)d_in[6];
    const float* bv = (const float*)d_in[7];
    const float* Wo = (const float*)d_in[8];
    const float* bo = (const float*)d_in[9];
    const float* ga = (const float*)d_in[10];
    const float* be = (const float*)d_in[11];

    float* out1 = (float*)d_out;
    float* out2 = out1 + (size_t)BB*SS*DD;

    void *pq, *pk, *pv, *ppb, *ppu, *pctx, *pres;
    cudaGetSymbolAddress(&pq,  g_q);
    cudaGetSymbolAddress(&pk,  g_k);
    cudaGetSymbolAddress(&pv,  g_v);
    cudaGetSymbolAddress(&ppb, g_pb);
    cudaGetSymbolAddress(&ppu, g_pu);
    cudaGetSymbolAddress(&pctx,g_ctx);
    cudaGetSymbolAddress(&pres,g_res);

    auto kproj  = mma_gemm<0>;
    auto koproj = mma_gemm<2>;
    const int SM_BIG = 2*(128+128)*36*4;   // 73728 B
    cudaFuncSetAttribute((const void*)kproj,  cudaFuncAttributeMaxDynamicSharedMemorySize, SM_BIG);
    cudaFuncSetAttribute((const void*)koproj, cudaFuncAttributeMaxDynamicSharedMemorySize, SM_BIG);

    dim3 blk(128);

    // QKV projections -> bf16 head layout (q pre-scaled by 1/8)
    kproj<<<dim3(8,32), blk, SM_BIG>>>(x, Wq, bq, nullptr, pq, BB*SS, DD, DD, 0.125f);
    kproj<<<dim3(8,32), blk, SM_BIG>>>(x, Wk, bk, nullptr, pk, BB*SS, DD, DD, 1.0f);
    kproj<<<dim3(8,32), blk, SM_BIG>>>(x, Wv, bv, nullptr, pv, BB*SS, DD, DD, 1.0f);

    // Fused scores + softmax (S never touches gmem)
    fused_scores_softmax<<<dim3(64, BHN), 256>>>(
        (const bf16*)pq, (const bf16*)pk,
        (bf16*)ppb, (bf16*)ppu, ts);

    // out2 = head-mean of unbiased probs
    out2_reduce<<<dim3(SS,BB), 256>>>((const bf16*)ppb, (const bf16*)ppu, out2);

    // ctx = probs @ V
    pv_bf16<<<dim3(8,BHN), 256>>>((const bf16*)ppb, (const bf16*)pv, (float*)pctx);

    // out projection + bias + residual
    koproj<<<dim3(8,32), blk, SM_BIG>>>((const float*)pctx, Wo, bo, x,
                                        pres, BB*SS, DD, DD, 1.0f);

    // LayerNorm -> output 1
    layernorm<<<dim3(BB*SS), 256>>>((const float*)pres, ga, be, out1);
}

// round 6
// speedup vs baseline: 1.0895x; 1.0895x over previous
#include <cuda_runtime.h>
#include <cuda_bf16.h>
#include <cstdint>
#include <math.h>

#define BB 4
#define SS 1024
#define DD 1024
#define NH 16
#define DKH 64
#define BHN (BB*NH)   // 64

typedef __nv_bfloat16 bf16;

// ---------------- device scratch ----------------
__device__ bf16  g_q[BB*NH*SS*DKH];                 // bf16 [b,h,s,dk], q pre-scaled 0.125
__device__ bf16  g_k[BB*NH*SS*DKH];
__device__ bf16  g_v[BB*NH*SS*DKH];
__device__ bf16  g_s[(size_t)BHN*SS*SS];            // raw scores bf16, 128MB
__device__ bf16  g_pb[(size_t)BHN*SS*SS];           // biased probs bf16, 128MB
__device__ float g_ctx[BB*SS*DD];
__device__ float g_res[BB*SS*DD];

// ---------------- helpers ----------------
__device__ __forceinline__ float warpSumT(float v){
    #pragma unroll
    for (int o=16;o;o>>=1) v += __shfl_xor_sync(0xffffffffu, v, o);
    return v;
}
__device__ __forceinline__ float warpMaxT(float v){
    #pragma unroll
    for (int o=16;o;o>>=1) v = fmaxf(v, __shfl_xor_sync(0xffffffffu, v, o));
    return v;
}
__device__ __forceinline__ float blockSum(float v, float* sh){
    v = warpSumT(v);
    int w = threadIdx.x >> 5, l = threadIdx.x & 31;
    if (l == 0) sh[w] = v;
    __syncthreads();
    float r = sh[0];
    #pragma unroll
    for (int i=1;i<8;i++) r += sh[i];
    __syncthreads();
    return r;
}
__device__ __forceinline__ void mma_tf32(float* d, const uint32_t* a, const uint32_t* b){
    asm volatile(
        "mma.sync.aligned.m16n8k8.row.col.f32.tf32.tf32.f32 "
        "{%0,%1,%2,%3}, {%4,%5,%6,%7}, {%8,%9}, {%0,%1,%2,%3};\n"
        : "+f"(d[0]), "+f"(d[1]), "+f"(d[2]), "+f"(d[3])
        : "r"(a[0]), "r"(a[1]), "r"(a[2]), "r"(a[3]),
          "r"(b[0]), "r"(b[1]));
}
__device__ __forceinline__ void mma_bf16(float* d, const uint32_t* a, const uint32_t* b){
    asm volatile(
        "mma.sync.aligned.m16n8k16.row.col.f32.bf16.bf16.f32 "
        "{%0,%1,%2,%3}, {%4,%5,%6,%7}, {%8,%9}, {%0,%1,%2,%3};\n"
        : "+f"(d[0]), "+f"(d[1]), "+f"(d[2]), "+f"(d[3])
        : "r"(a[0]), "r"(a[1]), "r"(a[2]), "r"(a[3]),
          "r"(b[0]), "r"(b[1]));
}
__device__ __forceinline__ void cpasync16(uint32_t s, const void* g){
    asm volatile("cp.async.cg.shared.global [%0], [%1], 16;\n" :: "r"(s), "l"(g));
}
__device__ __forceinline__ uint32_t smem_u32(const void* p){
    return (uint32_t)__cvta_generic_to_shared(p);
}
__device__ __forceinline__ uint32_t pack_bf16x2(float x, float y){
    __nv_bfloat162 a = __floats2bfloat162_rn(x, y);
    return *reinterpret_cast<uint32_t*>(&a);
}

// =====================================================================
// Merged QKV projection: virtual N = 3072.  Block bx in [0,24):
//   wsel = bx/8 chooses (Wq,bq,out_q,0.125) / (Wk,..) / (Wv,..)
// tf32 MMA, bf16 head-layout output.
// =====================================================================
__global__ void __launch_bounds__(128)
qkv_gemm(const float* __restrict__ A,
         const float* __restrict__ Wq, const float* __restrict__ Wk, const float* __restrict__ Wv,
         const float* __restrict__ bq, const float* __restrict__ bk, const float* __restrict__ bv,
         bf16* __restrict__ oq, bf16* __restrict__ ok, bf16* __restrict__ ov)
{
    constexpr int BM=128, BN=128, BK=32, S=36;
    constexpr int T=128, MT=4, NTL=8;
    constexpr int Kd=1024;

    extern __shared__ float sm[];
    float* As = sm;
    float* Bs = sm + 2*BM*S;

    const int tid = threadIdx.x;
    const int wsel = blockIdx.x >> 3;
    const int bm0 = blockIdx.y*BM, bn0 = (blockIdx.x & 7)*BN;

    const float* Bg   = (wsel==0) ? Wq : (wsel==1) ? Wk : Wv;
    const float* bias = (wsel==0) ? bq : (wsel==1) ? bk : bv;
    bf16* C           = (wsel==0) ? oq : (wsel==1) ? ok : ov;
    const float scale = (wsel==0) ? 0.125f : 1.0f;

    auto loadA = [&](int buf, int k0){
        #pragma unroll
        for (int i = 0; i < 8; i++){
            int id = tid + i*T;
            int r = id >> 3, ks = (id & 7)*4;
            cpasync16(smem_u32(&As[buf*BM*S + r*S + ks]),
                      A + (size_t)(bm0 + r)*Kd + k0 + ks);
        }
    };
    auto loadB = [&](int buf, int k0){
        #pragma unroll
        for (int i = 0; i < 8; i++){
            int id = tid + i*T;
            int r = id >> 3, ks = (id & 7)*4;
            cpasync16(smem_u32(&Bs[buf*BN*S + r*S + ks]),
                      Bg + (size_t)(bn0 + r)*Kd + k0 + ks);
        }
    };

    const int lane = tid & 31, g = lane >> 2, tg = lane & 3;
    const int warp = tid >> 5;
    const int wm = (warp >> 1) * 64, wn = (warp & 1) * 64;

    float acc[MT][NTL][4];
    #pragma unroll
    for (int i=0;i<MT;i++)
        #pragma unroll
        for (int j=0;j<NTL;j++)
            #pragma unroll
            for (int r=0;r<4;r++) acc[i][j][r] = 0.f;

    loadA(0, 0); loadB(0, 0);
    asm volatile("cp.async.commit_group;\n");

    for (int it = 0; it < Kd/BK; it++){
        int buf = it & 1;
        if (it + 1 < Kd/BK) {
            loadA(buf^1, (it+1)*BK); loadB(buf^1, (it+1)*BK);
            asm volatile("cp.async.commit_group;\n");
            asm volatile("cp.async.wait_group 1;\n");
        } else {
            asm volatile("cp.async.wait_group 0;\n");
        }
        __syncthreads();

        const float* Ab = As + buf*BM*S;
        const float* Bb = Bs + buf*BN*S;
        #pragma unroll
        for (int c = 0; c < BK/8; c++){
            uint32_t af[MT][4], bf[NTL][2];
            #pragma unroll
            for (int i = 0; i < MT; i++){
                const float* ap = Ab + (wm + i*16 + g)*S + c*8 + tg;
                af[i][0] = __float_as_uint(ap[0]);
                af[i][1] = __float_as_uint(ap[8*S]);
                af[i][2] = __float_as_uint(ap[4]);
                af[i][3] = __float_as_uint(ap[8*S + 4]);
            }
            #pragma unroll
            for (int j = 0; j < NTL; j++){
                const float* bp = Bb + (wn + j*8 + g)*S + c*8 + tg;
                bf[j][0] = __float_as_uint(bp[0]);
                bf[j][1] = __float_as_uint(bp[4]);
            }
            #pragma unroll
            for (int i = 0; i < MT; i++)
                #pragma unroll
                for (int j = 0; j < NTL; j++)
                    mma_tf32(acc[i][j], af[i], bf[j]);
        }
        __syncthreads();
    }

    #pragma unroll
    for (int i = 0; i < MT; i++){
        #pragma unroll
        for (int rr = 0; rr < 2; rr++){
            int row = bm0 + wm + i*16 + g + rr*8;
            #pragma unroll
            for (int j = 0; j < NTL; j++){
                int col = bn0 + wn + j*8 + 2*tg;
                float vx = (acc[i][j][rr*2+0] + bias[col])   * scale;
                float vy = (acc[i][j][rr*2+1] + bias[col+1]) * scale;
                int b = row >> 10, s = row & 1023;
                int h = col >> 6, dd = col & 63;
                uint32_t u = pack_bf16x2(vx, vy);
                *(uint32_t*)&C[((size_t)(b*NH + h) << 16) + s*DKH + dd] = u;
            }
        }
    }
}

// =====================================================================
// Out-projection (tf32): fp32 out, + bias + residual
// =====================================================================
__global__ void __launch_bounds__(128)
oproj_gemm(const float* __restrict__ A, const float* __restrict__ Bg,
           const float* __restrict__ bias, const float* __restrict__ resid,
           float* __restrict__ C)
{
    constexpr int BM=128, BN=128, BK=32, S=36;
    constexpr int T=128, MT=4, NTL=8;
    constexpr int Kd=1024, Nd=1024;

    extern __shared__ float sm[];
    float* As = sm;
    float* Bs = sm + 2*BM*S;

    const int tid = threadIdx.x;
    const int bm0 = blockIdx.y*BM, bn0 = blockIdx.x*BN;

    auto loadA = [&](int buf, int k0){
        #pragma unroll
        for (int i = 0; i < 8; i++){
            int id = tid + i*T;
            int r = id >> 3, ks = (id & 7)*4;
            cpasync16(smem_u32(&As[buf*BM*S + r*S + ks]),
                      A + (size_t)(bm0 + r)*Kd + k0 + ks);
        }
    };
    auto loadB = [&](int buf, int k0){
        #pragma unroll
        for (int i = 0; i < 8; i++){
            int id = tid + i*T;
            int r = id >> 3, ks = (id & 7)*4;
            cpasync16(smem_u32(&Bs[buf*BN*S + r*S + ks]),
                      Bg + (size_t)(bn0 + r)*Kd + k0 + ks);
        }
    };

    const int lane = tid & 31, g = lane >> 2, tg = lane & 3;
    const int warp = tid >> 5;
    const int wm = (warp >> 1) * 64, wn = (warp & 1) * 64;

    float acc[MT][NTL][4];
    #pragma unroll
    for (int i=0;i<MT;i++)
        #pragma unroll
        for (int j=0;j<NTL;j++)
            #pragma unroll
            for (int r=0;r<4;r++) acc[i][j][r] = 0.f;

    loadA(0, 0); loadB(0, 0);
    asm volatile("cp.async.commit_group;\n");

    for (int it = 0; it < Kd/BK; it++){
        int buf = it & 1;
        if (it + 1 < Kd/BK) {
            loadA(buf^1, (it+1)*BK); loadB(buf^1, (it+1)*BK);
            asm volatile("cp.async.commit_group;\n");
            asm volatile("cp.async.wait_group 1;\n");
        } else {
            asm volatile("cp.async.wait_group 0;\n");
        }
        __syncthreads();

        const float* Ab = As + buf*BM*S;
        const float* Bb = Bs + buf*BN*S;
        #pragma unroll
        for (int c = 0; c < BK/8; c++){
            uint32_t af[MT][4], bf[NTL][2];
            #pragma unroll
            for (int i = 0; i < MT; i++){
                const float* ap = Ab + (wm + i*16 + g)*S + c*8 + tg;
                af[i][0] = __float_as_uint(ap[0]);
                af[i][1] = __float_as_uint(ap[8*S]);
                af[i][2] = __float_as_uint(ap[4]);
                af[i][3] = __float_as_uint(ap[8*S + 4]);
            }
            #pragma unroll
            for (int j = 0; j < NTL; j++){
                const float* bp = Bb + (wn + j*8 + g)*S + c*8 + tg;
                bf[j][0] = __float_as_uint(bp[0]);
                bf[j][1] = __float_as_uint(bp[4]);
            }
            #pragma unroll
            for (int i = 0; i < MT; i++)
                #pragma unroll
                for (int j = 0; j < NTL; j++)
                    mma_tf32(acc[i][j], af[i], bf[j]);
        }
        __syncthreads();
    }

    #pragma unroll
    for (int i = 0; i < MT; i++){
        #pragma unroll
        for (int rr = 0; rr < 2; rr++){
            int row = bm0 + wm + i*16 + g + rr*8;
            #pragma unroll
            for (int j = 0; j < NTL; j++){
                int col = bn0 + wn + j*8 + 2*tg;
                size_t idx = (size_t)row*Nd + col;
                float2 r2 = *(const float2*)&resid[idx];
                float2 o = make_float2(acc[i][j][rr*2+0] + bias[col] + r2.x,
                                       acc[i][j][rr*2+1] + bias[col+1] + r2.y);
                *(float2*)&C[idx] = o;
            }
        }
    }
}

// =====================================================================
// Scores: per-bh  S[1024,1024](bf16) = Qb @ Kb^T (bf16 MMA, K=64 one-shot)
// =====================================================================
#define SCA 72
__global__ void __launch_bounds__(256)
scores_bf16(const bf16* __restrict__ Q, const bf16* __restrict__ K,
            bf16* __restrict__ Sc)
{
    __shared__ bf16 Qs[128*SCA];
    __shared__ bf16 Ks[128*SCA];

    const int bh = blockIdx.z;
    Q  += (size_t)bh << 16;
    K  += (size_t)bh << 16;
    Sc += (size_t)bh << 20;

    const int tid = threadIdx.x;
    const int bm0 = blockIdx.y*128, bn0 = blockIdx.x*128;

    #pragma unroll
    for (int i = 0; i < 4; i++){
        int id = tid + i*256;
        int r = id >> 3, c8 = (id & 7) << 3;
        cpasync16(smem_u32(&Qs[r*SCA + c8]), Q + (size_t)(bm0 + r)*DKH + c8);
    }
    #pragma unroll
    for (int i = 0; i < 4; i++){
        int id = tid + i*256;
        int r = id >> 3, c8 = (id & 7) << 3;
        cpasync16(smem_u32(&Ks[r*SCA + c8]), K + (size_t)(bn0 + r)*DKH + c8);
    }
    asm volatile("cp.async.commit_group;\n");
    asm volatile("cp.async.wait_group 0;\n");
    __syncthreads();

    const int lane = tid & 31, g = lane >> 2, tg = lane & 3;
    const int w = tid >> 5;
    const int wm = (w >> 2)*64, wn = (w & 3)*32;

    float acc[4][4][4];
    #pragma unroll
    for (int i=0;i<4;i++)
        #pragma unroll
        for (int j=0;j<4;j++)
            #pragma unroll
            for (int r=0;r<4;r++) acc[i][j][r]=0.f;

    #pragma unroll
    for (int kk = 0; kk < 4; kk++){
        uint32_t af[4][4], bfr[4][2];
        #pragma unroll
        for (int i = 0; i < 4; i++){
            const bf16* ap = &Qs[(wm + i*16 + g)*SCA + kk*16 + 2*tg];
            af[i][0] = *(const uint32_t*)(ap);
            af[i][1] = *(const uint32_t*)(ap + 8*SCA);
            af[i][2] = *(const uint32_t*)(ap + 8);
            af[i][3] = *(const uint32_t*)(ap + 8*SCA + 8);
        }
        #pragma unroll
        for (int j = 0; j < 4; j++){
            const bf16* bp = &Ks[(wn + j*8 + g)*SCA + kk*16 + 2*tg];
            bfr[j][0] = *(const uint32_t*)(bp);
            bfr[j][1] = *(const uint32_t*)(bp + 8);
        }
        #pragma unroll
        for (int i = 0; i < 4; i++)
            #pragma unroll
            for (int j = 0; j < 4; j++)
                mma_bf16(acc[i][j], af[i], bfr[j]);
    }

    #pragma unroll
    for (int i = 0; i < 4; i++){
        #pragma unroll
        for (int rr = 0; rr < 2; rr++){
            int row = bm0 + wm + i*16 + g + rr*8;
            #pragma unroll
            for (int j = 0; j < 4; j++){
                int col = bn0 + wn + j*8 + 2*tg;
                uint32_t u = pack_bf16x2(acc[i][j][rr*2+0], acc[i][j][rr*2+1]);
                *(uint32_t*)&Sc[((size_t)row << 10) + col] = u;
            }
        }
    }
}

// =====================================================================
// Softmax, warp-per-head-row, no block barriers in head loop.
// block = (b,row), 8 warps; warp w handles heads w and w+8.
// Writes biased probs bf16; accumulates unbiased head-mean -> out2.
// =====================================================================
__global__ void __launch_bounds__(256)
softmax_warp(const bf16* __restrict__ Sc, bf16* __restrict__ pb,
             float* __restrict__ out2, const int* __restrict__ ts_ptr)
{
    __shared__ float buf[8][1024];

    const int b   = blockIdx.y;
    const int row = blockIdx.x;
    const int tid = threadIdx.x;
    const int w   = tid >> 5, l = tid & 31;
    const bool dob = (ts_ptr[0] < 8) && (row < 64);

    float part[8][4];
    #pragma unroll
    for (int it=0;it<8;it++)
        #pragma unroll
        for (int j=0;j<4;j++) part[it][j]=0.f;

    #pragma unroll
    for (int hh = 0; hh < 2; hh++){
        const int h = w + hh*8;
        const size_t off = (((size_t)(b*NH + h)) << 20) + (((size_t)row) << 10);

        float v[8][4];
        #pragma unroll
        for (int it = 0; it < 8; it++){
            uint2 u = *(const uint2*)(Sc + off + l*4 + it*128);
            __nv_bfloat162 lo = *reinterpret_cast<__nv_bfloat162*>(&u.x);
            __nv_bfloat162 hi = *reinterpret_cast<__nv_bfloat162*>(&u.y);
            v[it][0] = __bfloat162float(lo.x); v[it][1] = __bfloat162float(lo.y);
            v[it][2] = __bfloat162float(hi.x); v[it][3] = __bfloat162float(hi.y);
        }

        // unbiased softmax
        float m = -1e30f;
        #pragma unroll
        for (int it=0;it<8;it++)
            m = fmaxf(m, fmaxf(fmaxf(v[it][0],v[it][1]), fmaxf(v[it][2],v[it][3])));
        m = warpMaxT(m);
        float e[8][4], s = 0.f;
        #pragma unroll
        for (int it=0;it<8;it++){
            #pragma unroll
            for (int j=0;j<4;j++){ e[it][j] = __expf(v[it][j]-m); s += e[it][j]; }
        }
        s = warpSumT(s);
        float inv = 1.0f / s;
        #pragma unroll
        for (int it=0;it<8;it++)
            #pragma unroll
            for (int j=0;j<4;j++) part[it][j] += e[it][j]*inv;

        bf16* dst = pb + off;
        if (dob){
            // biased: only cols<64 (it==0, l<16) change
            if (l < 16){
                #pragma unroll
                for (int j=0;j<4;j++){
                    int c = l*4 + j;
                    v[0][j] += 0.1f / (fabsf((float)(row - c)) + 1.0f);
                }
            }
            float m2 = -1e30f;
            #pragma unroll
            for (int it=0;it<8;it++)
                m2 = fmaxf(m2, fmaxf(fmaxf(v[it][0],v[it][1]), fmaxf(v[it][2],v[it][3])));
            m2 = warpMaxT(m2);
            float s2 = 0.f;
            #pragma unroll
            for (int it=0;it<8;it++){
                #pragma unroll
                for (int j=0;j<4;j++){ e[it][j] = __expf(v[it][j]-m2); s2 += e[it][j]; }
            }
            s2 = warpSumT(s2);
            float inv2 = 1.0f / s2;
            #pragma unroll
            for (int it=0;it<8;it++){
                uint2 u;
                u.x = pack_bf16x2(e[it][0]*inv2, e[it][1]*inv2);
                u.y = pack_bf16x2(e[it][2]*inv2, e[it][3]*inv2);
                *(uint2*)(dst + l*4 + it*128) = u;
            }
        } else {
            #pragma unroll
            for (int it=0;it<8;it++){
                uint2 u;
                u.x = pack_bf16x2(e[it][0]*inv, e[it][1]*inv);
                u.y = pack_bf16x2(e[it][2]*inv, e[it][3]*inv);
                *(uint2*)(dst + l*4 + it*128) = u;
            }
        }
    }

    // cross-warp out2 reduction
    #pragma unroll
    for (int it=0;it<8;it++)
        *(float4*)&buf[w][l*4 + it*128] = make_float4(part[it][0],part[it][1],part[it][2],part[it][3]);
    __syncthreads();

    int c0 = tid*4;
    float4 a = make_float4(0.f,0.f,0.f,0.f);
    #pragma unroll
    for (int ww=0; ww<8; ww++){
        float4 t = *(float4*)&buf[ww][c0];
        a.x += t.x; a.y += t.y; a.z += t.z; a.w += t.w;
    }
    const float k = 1.0f/16.0f;
    *(float4*)&out2[(((size_t)(b*SS + row)) << 10) + c0] =
        make_float4(a.x*k, a.y*k, a.z*k, a.w*k);
}

// =====================================================================
// PV: ctx[b,s,h*64+n] = probs(bf16) @ V(bf16)
// =====================================================================
__global__ void __launch_bounds__(256)
pv_bf16(const bf16* __restrict__ P, const bf16* __restrict__ V,
        float* __restrict__ ctx)
{
    constexpr int BK = 32, SA = 40;
    __shared__ bf16 As[2][128*SA];
    __shared__ bf16 Vs[2][64*SA];

    const int bh = blockIdx.y;
    P   += (size_t)bh << 20;
    V   += (size_t)bh << 16;
    ctx += ((size_t)(bh >> 4) << 20) + (size_t)(bh & 15)*64;

    const int tid = threadIdx.x;
    const int lane = tid & 31, g = lane >> 2, tg = lane & 3;
    const int w = tid >> 5;
    const int wm = (w >> 1) * 32, wn = (w & 1) * 32;
    const int m0 = blockIdx.x * 128;

    auto loadA = [&](int buf, int k0){
        #pragma unroll
        for (int i = 0; i < 2; i++){
            int id = tid + i*256;
            int r = id >> 2, c8 = (id & 3) << 3;
            cpasync16(smem_u32(&As[buf][r*SA + c8]),
                      P + (((size_t)(m0 + r)) << 10) + k0 + c8);
        }
    };
    auto loadV = [&](int buf, int k0){
        int k  = tid & 31;
        int n8 = (tid >> 5) * 8;
        union { uint4 u; bf16 h[8]; } val;
        val.u = *(const uint4*)(V + (((size_t)(k0 + k)) << 6) + n8);
        #pragma unroll
        for (int t = 0; t < 8; t++)
            Vs[buf][(n8 + t)*SA + k] = val.h[t];
    };

    float acc[2][4][4];
    #pragma unroll
    for (int i=0;i<2;i++)
        #pragma unroll
        for (int j=0;j<4;j++)
            #pragma unroll
            for (int r=0;r<4;r++) acc[i][j][r]=0.f;

    loadA(0, 0);
    asm volatile("cp.async.commit_group;\n");
    loadV(0, 0);

    for (int it = 0; it < SS/BK; it++){
        int buf = it & 1;
        if (it + 1 < SS/BK){
            loadA(buf^1, (it+1)*BK);
            asm volatile("cp.async.commit_group;\n");
            loadV(buf^1, (it+1)*BK);
            asm volatile("cp.async.wait_group 1;\n");
        } else {
            asm volatile("cp.async.wait_group 0;\n");
        }
        __syncthreads();

        #pragma unroll
        for (int kk = 0; kk < 2; kk++){
            uint32_t af[2][4], bfr[4][2];
            #pragma unroll
            for (int i = 0; i < 2; i++){
                const bf16* ap = &As[buf][(wm + i*16 + g)*SA + kk*16 + 2*tg];
                af[i][0] = *(const uint32_t*)(ap);
                af[i][1] = *(const uint32_t*)(ap + 8*SA);
                af[i][2] = *(const uint32_t*)(ap + 8);
                af[i][3] = *(const uint32_t*)(ap + 8*SA + 8);
            }
            #pragma unroll
            for (int j = 0; j < 4; j++){
                const bf16* bp = &Vs[buf][(wn + j*8 + g)*SA + kk*16 + 2*tg];
                bfr[j][0] = *(const uint32_t*)(bp);
                bfr[j][1] = *(const uint32_t*)(bp + 8);
            }
            #pragma unroll
            for (int i = 0; i < 2; i++)
                #pragma unroll
                for (int j = 0; j < 4; j++)
                    mma_bf16(acc[i][j], af[i], bfr[j]);
        }
        __syncthreads();
    }

    #pragma unroll
    for (int i = 0; i < 2; i++){
        #pragma unroll
        for (int rr = 0; rr < 2; rr++){
            int row = m0 + wm + i*16 + g + rr*8;
            #pragma unroll
            for (int j = 0; j < 4; j++){
                int col = wn + j*8 + 2*tg;
                float2 o = make_float2(acc[i][j][rr*2+0], acc[i][j][rr*2+1]);
                *(float2*)&ctx[((size_t)row << 10) + col] = o;
            }
        }
    }
}

// ---------------- LayerNorm --------------------------------------------------
__global__ void __launch_bounds__(256)
layernorm(const float* __restrict__ R, const float* __restrict__ gamma,
          const float* __restrict__ beta, float* __restrict__ out)
{
    __shared__ float red[8];
    int row = blockIdx.x;
    int tid = threadIdx.x;
    const float* src = R + ((size_t)row << 10);
    float v[4];
    #pragma unroll
    for (int j=0;j<4;j++) v[j] = src[tid + (j<<8)];
    float s = v[0]+v[1]+v[2]+v[3];
    s = blockSum(s, red);
    float mu = s * (1.0f/1024.0f);
    float q = 0.f;
    #pragma unroll
    for (int j=0;j<4;j++) { float d = v[j]-mu; q += d*d; }
    q = blockSum(q, red);
    float inv = rsqrtf(q * (1.0f/1024.0f) + 1e-5f);
    #pragma unroll
    for (int j=0;j<4;j++) {
        int c = tid + (j<<8);
        out[((size_t)row << 10) + c] = (v[j]-mu)*inv*gamma[c] + beta[c];
    }
}

// ---------------- launch -----------------------------------------------------
extern "C" void kernel_launch(void* const* d_in, const int* in_sizes, int n_in,
                              void* d_out, int out_size)
{
    const float* x  = (const float*)d_in[0];
    const int*   ts = (const int*)  d_in[1];
    const float* Wq = (const float*)d_in[2];
    const float* bq = (const float*)d_in[3];
    const float* Wk = (const float*)d_in[4];
    const float* bk = (const float*)d_in[5];
    const float* Wv = (const float*)d_in[6];
    const float* bv = (const float*)d_in[7];
    const float* Wo = (const float*)d_in[8];
    const float* bo = (const float*)d_in[9];
    const float* ga = (const float*)d_in[10];
    const float* be = (const float*)d_in[11];

    float* out1 = (float*)d_out;
    float* out2 = out1 + (size_t)BB*SS*DD;

    void *pq, *pk, *pv, *psc, *ppb, *pctx, *pres;
    cudaGetSymbolAddress(&pq,  g_q);
    cudaGetSymbolAddress(&pk,  g_k);
    cudaGetSymbolAddress(&pv,  g_v);
    cudaGetSymbolAddress(&psc, g_s);
    cudaGetSymbolAddress(&ppb, g_pb);
    cudaGetSymbolAddress(&pctx,g_ctx);
    cudaGetSymbolAddress(&pres,g_res);

    const int SM_BIG = 2*(128+128)*36*4;   // 73728 B
    cudaFuncSetAttribute((const void*)qkv_gemm,  cudaFuncAttributeMaxDynamicSharedMemorySize, SM_BIG);
    cudaFuncSetAttribute((const void*)oproj_gemm, cudaFuncAttributeMaxDynamicSharedMemorySize, SM_BIG);

    // Merged QKV projection (virtual N=3072)
    qkv_gemm<<<dim3(24,32), 128, SM_BIG>>>(x, Wq, Wk, Wv, bq, bk, bv,
                                           (bf16*)pq, (bf16*)pk, (bf16*)pv);

    // Raw scores (bf16) per bh
    scores_bf16<<<dim3(8,8,BHN), 256>>>((const bf16*)pq, (const bf16*)pk,
                                        (bf16*)psc);

    // Softmax (warp-per-head-row): biased probs -> pb, head-mean unbiased -> out2
    softmax_warp<<<dim3(SS,BB), 256>>>((const bf16*)psc, (bf16*)ppb, out2, ts);

    // ctx = probs @ V
    pv_bf16<<<dim3(8,BHN), 256>>>((const bf16*)ppb, (const bf16*)pv, (float*)pctx);

    // out projection + bias + residual
    oproj_gemm<<<dim3(8,32), 128, SM_BIG>>>((const float*)pctx, Wo, bo, x,
                                            (float*)pres);

    // LayerNorm -> output 1
    layernorm<<<dim3(BB*SS), 256>>>((const float*)pres, ga, be, out1);
}

// round 8
// speedup vs baseline: 1.1625x; 1.0670x over previous
#include <cuda_runtime.h>
#include <cuda_bf16.h>
#include <cstdint>
#include <math.h>

#define BB 4
#define SS 1024
#define DD 1024
#define NH 16
#define DKH 64
#define BHN (BB*NH)   // 64
#define FST 72        // smem stride (bf16) for 64-wide tiles
#define SHF 4.0f      // constant softmax shift (cancels exactly in normalization)

typedef __nv_bfloat16 bf16;

// ---------------- device scratch ----------------
__device__ bf16  g_q[BB*NH*SS*DKH];       // [b,h,s,dk], q pre-scaled 0.125
__device__ bf16  g_k[BB*NH*SS*DKH];
__device__ bf16  g_v[BB*NH*SS*DKH];
__device__ bf16  g_vt[BB*NH*DKH*SS];      // V transposed per head: [bh][dk][s]
__device__ float g_lu[BHN*SS];            // unbiased row sums (shifted)
__device__ float g_ctx[BB*SS*DD];
__device__ float g_res[BB*SS*DD];
__device__ float g_o2p[(size_t)4*BB*SS*SS];  // out2 partials [hq][b][row][col], 64MB

// ---------------- helpers ----------------
__device__ __forceinline__ float warpSumT(float v){
    #pragma unroll
    for (int o=16;o;o>>=1) v += __shfl_xor_sync(0xffffffffu, v, o);
    return v;
}
__device__ __forceinline__ float blockSum(float v, float* sh){
    v = warpSumT(v);
    int w = threadIdx.x >> 5, l = threadIdx.x & 31;
    if (l == 0) sh[w] = v;
    __syncthreads();
    float r = sh[0];
    #pragma unroll
    for (int i=1;i<8;i++) r += sh[i];
    __syncthreads();
    return r;
}
__device__ __forceinline__ void mma_tf32(float* d, const uint32_t* a, const uint32_t* b){
    asm volatile(
        "mma.sync.aligned.m16n8k8.row.col.f32.tf32.tf32.f32 "
        "{%0,%1,%2,%3}, {%4,%5,%6,%7}, {%8,%9}, {%0,%1,%2,%3};\n"
        : "+f"(d[0]), "+f"(d[1]), "+f"(d[2]), "+f"(d[3])
        : "r"(a[0]), "r"(a[1]), "r"(a[2]), "r"(a[3]),
          "r"(b[0]), "r"(b[1]));
}
__device__ __forceinline__ void mma_bf16(float* d, const uint32_t* a, const uint32_t* b){
    asm volatile(
        "mma.sync.aligned.m16n8k16.row.col.f32.bf16.bf16.f32 "
        "{%0,%1,%2,%3}, {%4,%5,%6,%7}, {%8,%9}, {%0,%1,%2,%3};\n"
        : "+f"(d[0]), "+f"(d[1]), "+f"(d[2]), "+f"(d[3])
        : "r"(a[0]), "r"(a[1]), "r"(a[2]), "r"(a[3]),
          "r"(b[0]), "r"(b[1]));
}
__device__ __forceinline__ void cpasync16(uint32_t s, const void* g){
    asm volatile("cp.async.cg.shared.global [%0], [%1], 16;\n" :: "r"(s), "l"(g));
}
__device__ __forceinline__ uint32_t smem_u32(const void* p){
    return (uint32_t)__cvta_generic_to_shared(p);
}
__device__ __forceinline__ uint32_t pack_bf16x2(float x, float y){
    __nv_bfloat162 a = __floats2bfloat162_rn(x, y);
    return *reinterpret_cast<uint32_t*>(&a);
}

// =====================================================================
// Merged QKV projection (tf32), bf16 head-layout output.
// =====================================================================
__global__ void __launch_bounds__(128)
qkv_gemm(const float* __restrict__ A,
         const float* __restrict__ Wq, const float* __restrict__ Wk, const float* __restrict__ Wv,
         const float* __restrict__ bq, const float* __restrict__ bk, const float* __restrict__ bv,
         bf16* __restrict__ oq, bf16* __restrict__ ok, bf16* __restrict__ ov)
{
    constexpr int BM=128, BN=128, BK=32, S=36;
    constexpr int T=128, MT=4, NTL=8;
    constexpr int Kd=1024;

    extern __shared__ float sm[];
    float* As = sm;
    float* Bs = sm + 2*BM*S;

    const int tid = threadIdx.x;
    const int wsel = blockIdx.x >> 3;
    const int bm0 = blockIdx.y*BM, bn0 = (blockIdx.x & 7)*BN;

    const float* Bg   = (wsel==0) ? Wq : (wsel==1) ? Wk : Wv;
    const float* bias = (wsel==0) ? bq : (wsel==1) ? bk : bv;
    bf16* C           = (wsel==0) ? oq : (wsel==1) ? ok : ov;
    const float scale = (wsel==0) ? 0.125f : 1.0f;

    auto loadA = [&](int buf, int k0){
        #pragma unroll
        for (int i = 0; i < 8; i++){
            int id = tid + i*T;
            int r = id >> 3, ks = (id & 7)*4;
            cpasync16(smem_u32(&As[buf*BM*S + r*S + ks]),
                      A + (size_t)(bm0 + r)*Kd + k0 + ks);
        }
    };
    auto loadB = [&](int buf, int k0){
        #pragma unroll
        for (int i = 0; i < 8; i++){
            int id = tid + i*T;
            int r = id >> 3, ks = (id & 7)*4;
            cpasync16(smem_u32(&Bs[buf*BN*S + r*S + ks]),
                      Bg + (size_t)(bn0 + r)*Kd + k0 + ks);
        }
    };

    const int lane = tid & 31, g = lane >> 2, tg = lane & 3;
    const int warp = tid >> 5;
    const int wm = (warp >> 1) * 64, wn = (warp & 1) * 64;

    float acc[MT][NTL][4];
    #pragma unroll
    for (int i=0;i<MT;i++)
        #pragma unroll
        for (int j=0;j<NTL;j++)
            #pragma unroll
            for (int r=0;r<4;r++) acc[i][j][r] = 0.f;

    loadA(0, 0); loadB(0, 0);
    asm volatile("cp.async.commit_group;\n");

    for (int it = 0; it < Kd/BK; it++){
        int buf = it & 1;
        if (it + 1 < Kd/BK) {
            loadA(buf^1, (it+1)*BK); loadB(buf^1, (it+1)*BK);
            asm volatile("cp.async.commit_group;\n");
            asm volatile("cp.async.wait_group 1;\n");
        } else {
            asm volatile("cp.async.wait_group 0;\n");
        }
        __syncthreads();

        const float* Ab = As + buf*BM*S;
        const float* Bb = Bs + buf*BN*S;
        #pragma unroll
        for (int c = 0; c < BK/8; c++){
            uint32_t af[MT][4], bf[NTL][2];
            #pragma unroll
            for (int i = 0; i < MT; i++){
                const float* ap = Ab + (wm + i*16 + g)*S + c*8 + tg;
                af[i][0] = __float_as_uint(ap[0]);
                af[i][1] = __float_as_uint(ap[8*S]);
                af[i][2] = __float_as_uint(ap[4]);
                af[i][3] = __float_as_uint(ap[8*S + 4]);
            }
            #pragma unroll
            for (int j = 0; j < NTL; j++){
                const float* bp = Bb + (wn + j*8 + g)*S + c*8 + tg;
                bf[j][0] = __float_as_uint(bp[0]);
                bf[j][1] = __float_as_uint(bp[4]);
            }
            #pragma unroll
            for (int i = 0; i < MT; i++)
                #pragma unroll
                for (int j = 0; j < NTL; j++)
                    mma_tf32(acc[i][j], af[i], bf[j]);
        }
        __syncthreads();
    }

    #pragma unroll
    for (int i = 0; i < MT; i++){
        #pragma unroll
        for (int rr = 0; rr < 2; rr++){
            int row = bm0 + wm + i*16 + g + rr*8;
            #pragma unroll
            for (int j = 0; j < NTL; j++){
                int col = bn0 + wn + j*8 + 2*tg;
                float vx = (acc[i][j][rr*2+0] + bias[col])   * scale;
                float vy = (acc[i][j][rr*2+1] + bias[col+1]) * scale;
                int b = row >> 10, s = row & 1023;
                int h = col >> 6, dd = col & 63;
                uint32_t u = pack_bf16x2(vx, vy);
                *(uint32_t*)&C[((size_t)(b*NH + h) << 16) + s*DKH + dd] = u;
            }
        }
    }
}

// =====================================================================
// V transpose per head: g_v[bh][s][dk] -> g_vt[bh][dk][s]
// =====================================================================
__global__ void __launch_bounds__(256)
v_transpose(const bf16* __restrict__ V, bf16* __restrict__ Vt)
{
    __shared__ bf16 t[64][FST];
    const int sc = blockIdx.x, bh = blockIdx.y;
    const int tid = threadIdx.x;
    const bf16* src = V + ((size_t)bh << 16) + sc*64*DKH;

    #pragma unroll
    for (int i = 0; i < 2; i++){
        int id = tid + (i << 8);
        int r = id >> 3, c8 = (id & 7) << 3;
        *(uint4*)&t[r][c8] = *(const uint4*)(src + r*DKH + c8);
    }
    __syncthreads();

    bf16* dst = Vt + ((size_t)bh << 16) + sc*64;
    #pragma unroll
    for (int i = 0; i < 2; i++){
        int id = tid + (i << 8);
        int r = id >> 3, c8 = (id & 7) << 3;   // r = dk row, c8 = s cols
        union { uint4 u; bf16 h[8]; } o;
        #pragma unroll
        for (int tj = 0; tj < 8; tj++) o.h[tj] = t[c8 + tj][r];
        *(uint4*)(dst + (size_t)r*SS + c8) = o.u;
    }
}

// =====================================================================
// FLASH: per (mtile=128, bh). S = Q@K^T in regs (fp32), constant-shift
// softmax, P(bf16)@V accumulated in regs. Writes ctx + unbiased row sums.
// =====================================================================
__global__ void __launch_bounds__(256)
flash_pv(const bf16* __restrict__ Q, const bf16* __restrict__ K,
         const bf16* __restrict__ Vt, float* __restrict__ ctx,
         float* __restrict__ lu_out, const int* __restrict__ ts_ptr)
{
    extern __shared__ bf16 fsm[];
    bf16* Qs = fsm;                       // 128*FST
    bf16* Ks = fsm + 128*FST;             // 2*64*FST
    bf16* Vs = fsm + 128*FST + 2*64*FST;  // 2*64*FST

    const int tid = threadIdx.x;
    const int lane = tid & 31, g = lane >> 2, tg = lane & 3;
    const int w = tid >> 5;
    const int mt = blockIdx.x, bh = blockIdx.y;
    const int m0 = mt*128;

    const bf16* Qb = Q  + ((size_t)bh << 16) + (size_t)m0*DKH;
    const bf16* Kb = K  + ((size_t)bh << 16);
    const bf16* Vb = Vt + ((size_t)bh << 16);

    #pragma unroll
    for (int i = 0; i < 4; i++){
        int id = tid + (i << 8);
        int r = id >> 3, c8 = (id & 7) << 3;
        cpasync16(smem_u32(&Qs[r*FST + c8]), Qb + r*DKH + c8);
    }
    auto loadK = [&](int buf, int k0){
        #pragma unroll
        for (int i = 0; i < 2; i++){
            int id = tid + (i << 8);
            int r = id >> 3, c8 = (id & 7) << 3;
            cpasync16(smem_u32(&Ks[buf*64*FST + r*FST + c8]),
                      Kb + (size_t)(k0 + r)*DKH + c8);
        }
    };
    auto loadV = [&](int buf, int k0){
        #pragma unroll
        for (int i = 0; i < 2; i++){
            int id = tid + (i << 8);
            int r = id >> 3, c8 = (id & 7) << 3;   // r = dk row
            cpasync16(smem_u32(&Vs[buf*64*FST + r*FST + c8]),
                      Vb + (size_t)r*SS + k0 + c8);
        }
    };
    loadK(0, 0); loadV(0, 0);
    asm volatile("cp.async.commit_group;\n");

    float oacc[8][4];
    #pragma unroll
    for (int j=0;j<8;j++)
        #pragma unroll
        for (int v=0;v<4;v++) oacc[j][v]=0.f;
    float l0=0.f, l1=0.f, lu0=0.f, lu1=0.f;

    const bool dob = (ts_ptr[0] < 8) && (mt == 0) && (w < 4);
    const int row0 = m0 + w*16 + g, row1 = row0 + 8;

    uint32_t qf[4][4];
    bool qldd = false;

    for (int c = 0; c < 16; c++){
        int buf = c & 1;
        if (c + 1 < 16){
            loadK(buf^1, (c+1)*64); loadV(buf^1, (c+1)*64);
            asm volatile("cp.async.commit_group;\n");
            asm volatile("cp.async.wait_group 1;\n");
        } else {
            asm volatile("cp.async.wait_group 0;\n");
        }
        __syncthreads();

        if (!qldd){
            #pragma unroll
            for (int kk = 0; kk < 4; kk++){
                const bf16* ap = &Qs[(w*16 + g)*FST + kk*16 + 2*tg];
                qf[kk][0] = *(const uint32_t*)(ap);
                qf[kk][1] = *(const uint32_t*)(ap + 8*FST);
                qf[kk][2] = *(const uint32_t*)(ap + 8);
                qf[kk][3] = *(const uint32_t*)(ap + 8*FST + 8);
            }
            qldd = true;
        }

        const bf16* Kc = Ks + buf*64*FST;
        const bf16* Vc = Vs + buf*64*FST;

        float sacc[8][4];
        #pragma unroll
        for (int j=0;j<8;j++)
            #pragma unroll
            for (int v=0;v<4;v++) sacc[j][v]=0.f;

        #pragma unroll
        for (int kk = 0; kk < 4; kk++){
            #pragma unroll
            for (int j = 0; j < 8; j++){
                const bf16* bp = &Kc[(j*8 + g)*FST + kk*16 + 2*tg];
                uint32_t bfr[2] = { *(const uint32_t*)(bp), *(const uint32_t*)(bp + 8) };
                mma_bf16(sacc[j], qf[kk], bfr);
            }
        }

        const bool bchunk = dob && (c == 0);
        if (bchunk){
            float u0=0.f, u1=0.f;
            #pragma unroll
            for (int j = 0; j < 8; j++){
                u0 += __expf(sacc[j][0]-SHF) + __expf(sacc[j][1]-SHF);
                u1 += __expf(sacc[j][2]-SHF) + __expf(sacc[j][3]-SHF);
            }
            lu0 += u0; lu1 += u1;
            #pragma unroll
            for (int j = 0; j < 8; j++){
                int col = j*8 + 2*tg;
                sacc[j][0] += 0.1f / (fabsf((float)(row0 - col))     + 1.0f);
                sacc[j][1] += 0.1f / (fabsf((float)(row0 - col - 1)) + 1.0f);
                sacc[j][2] += 0.1f / (fabsf((float)(row1 - col))     + 1.0f);
                sacc[j][3] += 0.1f / (fabsf((float)(row1 - col - 1)) + 1.0f);
            }
        }

        uint32_t pk0[8], pk1[8];
        float r0=0.f, r1=0.f;
        #pragma unroll
        for (int j = 0; j < 8; j++){
            float p0 = __expf(sacc[j][0]-SHF), p1 = __expf(sacc[j][1]-SHF);
            float p2 = __expf(sacc[j][2]-SHF), p3 = __expf(sacc[j][3]-SHF);
            r0 += p0 + p1; r1 += p2 + p3;
            pk0[j] = pack_bf16x2(p0, p1);
            pk1[j] = pack_bf16x2(p2, p3);
        }
        l0 += r0; l1 += r1;
        if (!bchunk){ lu0 += r0; lu1 += r1; }

        #pragma unroll
        for (int kk = 0; kk < 4; kk++){
            uint32_t a[4] = { pk0[2*kk], pk1[2*kk], pk0[2*kk+1], pk1[2*kk+1] };
            #pragma unroll
            for (int j = 0; j < 8; j++){
                const bf16* bp = &Vc[(j*8 + g)*FST + kk*16 + 2*tg];
                uint32_t b2[2] = { *(const uint32_t*)(bp), *(const uint32_t*)(bp + 8) };
                mma_bf16(oacc[j], a, b2);
            }
        }
        __syncthreads();
    }

    #pragma unroll
    for (int o = 1; o < 4; o <<= 1){
        l0  += __shfl_xor_sync(0xffffffffu, l0,  o);
        l1  += __shfl_xor_sync(0xffffffffu, l1,  o);
        lu0 += __shfl_xor_sync(0xffffffffu, lu0, o);
        lu1 += __shfl_xor_sync(0xffffffffu, lu1, o);
    }
    float i0 = 1.0f / l0, i1 = 1.0f / l1;

    float* cb = ctx + ((size_t)(bh >> 4) << 20) + (size_t)(bh & 15)*64;
    #pragma unroll
    for (int j = 0; j < 8; j++){
        int col = j*8 + 2*tg;
        *(float2*)&cb[(size_t)row0*DD + col] = make_float2(oacc[j][0]*i0, oacc[j][1]*i0);
        *(float2*)&cb[(size_t)row1*DD + col] = make_float2(oacc[j][2]*i1, oacc[j][3]*i1);
    }
    if (tg == 0){
        lu_out[bh*SS + row0] = lu0;
        lu_out[bh*SS + row1] = lu1;
    }
}

// =====================================================================
// out2 partials: per (mtile, hq, b): recompute S for 4 heads, accumulate
// p_u = exp(s-SHF)/lu.  grid (8, 4, 4), 256 threads.
// =====================================================================
__global__ void __launch_bounds__(256)
out2_part(const bf16* __restrict__ Q, const bf16* __restrict__ K,
          const float* __restrict__ lu, float* __restrict__ part)
{
    extern __shared__ char o2sm[];
    bf16*  Qs4   = (bf16*)o2sm;                          // 4*128*FST
    bf16*  Ks    = (bf16*)(o2sm + 4*128*FST*2);          // 2*64*FST
    float* luinv = (float*)(o2sm + 4*128*FST*2 + 2*64*FST*2);  // 512

    const int tid = threadIdx.x;
    const int lane = tid & 31, g = lane >> 2, tg = lane & 3;
    const int w = tid >> 5;
    const int mt = blockIdx.x, hq = blockIdx.y, b = blockIdx.z;
    const int m0 = mt*128;

    #pragma unroll
    for (int i = 0; i < 16; i++){
        int id = tid + (i << 8);
        int hi = id >> 10, rr = (id >> 3) & 127, c8 = (id & 7) << 3;
        cpasync16(smem_u32(&Qs4[hi*128*FST + rr*FST + c8]),
                  Q + ((size_t)(b*NH + hq*4 + hi) << 16) + (size_t)(m0 + rr)*DKH + c8);
    }
    #pragma unroll
    for (int i = 0; i < 2; i++){
        int e = tid + (i << 8);     // e = hi*128 + r
        int hi = e >> 7, r = e & 127;
        luinv[e] = 1.0f / lu[(b*NH + hq*4 + hi)*SS + m0 + r];
    }
    auto loadK = [&](int buf, int idx){
        int hi = idx & 3, c = idx >> 2;
        const bf16* src = K + ((size_t)(b*NH + hq*4 + hi) << 16) + (size_t)(c*64)*DKH;
        #pragma unroll
        for (int i = 0; i < 2; i++){
            int id = tid + (i << 8);
            int r = id >> 3, c8 = (id & 7) << 3;
            cpasync16(smem_u32(&Ks[buf*64*FST + r*FST + c8]), src + (size_t)r*DKH + c8);
        }
    };
    loadK(0, 0);
    asm volatile("cp.async.commit_group;\n");

    float acc[8][4];
    float* pbase = part + ((size_t)hq << 22) + ((size_t)b << 20);

    for (int idx = 0; idx < 64; idx++){
        int buf = idx & 1;
        if (idx + 1 < 64){
            loadK(buf^1, idx+1);
            asm volatile("cp.async.commit_group;\n");
            asm volatile("cp.async.wait_group 1;\n");
        } else {
            asm volatile("cp.async.wait_group 0;\n");
        }
        __syncthreads();

        const int c = idx >> 2, hi = idx & 3;
        if (hi == 0){
            #pragma unroll
            for (int j=0;j<8;j++)
                #pragma unroll
                for (int v=0;v<4;v++) acc[j][v]=0.f;
        }

        uint32_t qf[4][4];
        const bf16* qb = Qs4 + hi*128*FST;
        #pragma unroll
        for (int kk = 0; kk < 4; kk++){
            const bf16* ap = &qb[(w*16 + g)*FST + kk*16 + 2*tg];
            qf[kk][0] = *(const uint32_t*)(ap);
            qf[kk][1] = *(const uint32_t*)(ap + 8*FST);
            qf[kk][2] = *(const uint32_t*)(ap + 8);
            qf[kk][3] = *(const uint32_t*)(ap + 8*FST + 8);
        }

        float sacc[8][4];
        #pragma unroll
        for (int j=0;j<8;j++)
            #pragma unroll
            for (int v=0;v<4;v++) sacc[j][v]=0.f;

        const bf16* Kc = Ks + buf*64*FST;
        #pragma unroll
        for (int kk = 0; kk < 4; kk++){
            #pragma unroll
            for (int j = 0; j < 8; j++){
                const bf16* bp = &Kc[(j*8 + g)*FST + kk*16 + 2*tg];
                uint32_t bfr[2] = { *(const uint32_t*)(bp), *(const uint32_t*)(bp + 8) };
                mma_bf16(sacc[j], qf[kk], bfr);
            }
        }

        float li0 = luinv[hi*128 + w*16 + g];
        float li1 = luinv[hi*128 + w*16 + g + 8];
        #pragma unroll
        for (int j = 0; j < 8; j++){
            acc[j][0] += __expf(sacc[j][0]-SHF)*li0;
            acc[j][1] += __expf(sacc[j][1]-SHF)*li0;
            acc[j][2] += __expf(sacc[j][2]-SHF)*li1;
            acc[j][3] += __expf(sacc[j][3]-SHF)*li1;
        }

        if (hi == 3){
            int row0 = m0 + w*16 + g, row1 = row0 + 8;
            #pragma unroll
            for (int j = 0; j < 8; j++){
                int col = c*64 + j*8 + 2*tg;
                *(float2*)&pbase[(size_t)row0*SS + col] = make_float2(acc[j][0], acc[j][1]);
                *(float2*)&pbase[(size_t)row1*SS + col] = make_float2(acc[j][2], acc[j][3]);
            }
        }
        __syncthreads();
    }
}

// ---------------- out2 reduce: sum 4 hq-partials, /16 ----------------
// part layout: [hq][b*row*col] with hq stride (1<<22) ELEMENTS.
// out2 has (1<<22) elements; grid = (1<<22)/(256*4) = 4096 blocks.
__global__ void __launch_bounds__(256)
out2_reduce(const float* __restrict__ part, float* __restrict__ out2)
{
    size_t i = ((size_t)blockIdx.x*256 + threadIdx.x) * 4;
    float4 a  = *(const float4*)(part + i);
    float4 b4 = *(const float4*)(part + (1ull<<22) + i);
    float4 c4 = *(const float4*)(part + (2ull<<22) + i);
    float4 d4 = *(const float4*)(part + (3ull<<22) + i);
    const float k = 1.0f/16.0f;
    float4 o = make_float4((a.x+b4.x+c4.x+d4.x)*k, (a.y+b4.y+c4.y+d4.y)*k,
                           (a.z+b4.z+c4.z+d4.z)*k, (a.w+b4.w+c4.w+d4.w)*k);
    *(float4*)(out2 + i) = o;
}

// =====================================================================
// Out-projection (tf32): fp32 out, + bias + residual
// =====================================================================
__global__ void __launch_bounds__(128)
oproj_gemm(const float* __restrict__ A, const float* __restrict__ Bg,
           const float* __restrict__ bias, const float* __restrict__ resid,
           float* __restrict__ C)
{
    constexpr int BM=128, BN=128, BK=32, S=36;
    constexpr int T=128, MT=4, NTL=8;
    constexpr int Kd=1024, Nd=1024;

    extern __shared__ float sm[];
    float* As = sm;
    float* Bs = sm + 2*BM*S;

    const int tid = threadIdx.x;
    const int bm0 = blockIdx.y*BM, bn0 = blockIdx.x*BN;

    auto loadA = [&](int buf, int k0){
        #pragma unroll
        for (int i = 0; i < 8; i++){
            int id = tid + i*T;
            int r = id >> 3, ks = (id & 7)*4;
            cpasync16(smem_u32(&As[buf*BM*S + r*S + ks]),
                      A + (size_t)(bm0 + r)*Kd + k0 + ks);
        }
    };
    auto loadB = [&](int buf, int k0){
        #pragma unroll
        for (int i = 0; i < 8; i++){
            int id = tid + i*T;
            int r = id >> 3, ks = (id & 7)*4;
            cpasync16(smem_u32(&Bs[buf*BN*S + r*S + ks]),
                      Bg + (size_t)(bn0 + r)*Kd + k0 + ks);
        }
    };

    const int lane = tid & 31, g = lane >> 2, tg = lane & 3;
    const int warp = tid >> 5;
    const int wm = (warp >> 1) * 64, wn = (warp & 1) * 64;

    float acc[MT][NTL][4];
    #pragma unroll
    for (int i=0;i<MT;i++)
        #pragma unroll
        for (int j=0;j<NTL;j++)
            #pragma unroll
            for (int r=0;r<4;r++) acc[i][j][r] = 0.f;

    loadA(0, 0); loadB(0, 0);
    asm volatile("cp.async.commit_group;\n");

    for (int it = 0; it < Kd/BK; it++){
        int buf = it & 1;
        if (it + 1 < Kd/BK) {
            loadA(buf^1, (it+1)*BK); loadB(buf^1, (it+1)*BK);
            asm volatile("cp.async.commit_group;\n");
            asm volatile("cp.async.wait_group 1;\n");
        } else {
            asm volatile("cp.async.wait_group 0;\n");
        }
        __syncthreads();

        const float* Ab = As + buf*BM*S;
        const float* Bb = Bs + buf*BN*S;
        #pragma unroll
        for (int c = 0; c < BK/8; c++){
            uint32_t af[MT][4], bf[NTL][2];
            #pragma unroll
            for (int i = 0; i < MT; i++){
                const float* ap = Ab + (wm + i*16 + g)*S + c*8 + tg;
                af[i][0] = __float_as_uint(ap[0]);
                af[i][1] = __float_as_uint(ap[8*S]);
                af[i][2] = __float_as_uint(ap[4]);
                af[i][3] = __float_as_uint(ap[8*S + 4]);
            }
            #pragma unroll
            for (int j = 0; j < NTL; j++){
                const float* bp = Bb + (wn + j*8 + g)*S + c*8 + tg;
                bf[j][0] = __float_as_uint(bp[0]);
                bf[j][1] = __float_as_uint(bp[4]);
            }
            #pragma unroll
            for (int i = 0; i < MT; i++)
                #pragma unroll
                for (int j = 0; j < NTL; j++)
                    mma_tf32(acc[i][j], af[i], bf[j]);
        }
        __syncthreads();
    }

    #pragma unroll
    for (int i = 0; i < MT; i++){
        #pragma unroll
        for (int rr = 0; rr < 2; rr++){
            int row = bm0 + wm + i*16 + g + rr*8;
            #pragma unroll
            for (int j = 0; j < NTL; j++){
                int col = bn0 + wn + j*8 + 2*tg;
                size_t idx = (size_t)row*Nd + col;
                float2 r2 = *(const float2*)&resid[idx];
                float2 o = make_float2(acc[i][j][rr*2+0] + bias[col] + r2.x,
                                       acc[i][j][rr*2+1] + bias[col+1] + r2.y);
                *(float2*)&C[idx] = o;
            }
        }
    }
}

// ---------------- LayerNorm --------------------------------------------------
__global__ void __launch_bounds__(256)
layernorm(const float* __restrict__ R, const float* __restrict__ gamma,
          const float* __restrict__ beta, float* __restrict__ out)
{
    __shared__ float red[8];
    int row = blockIdx.x;
    int tid = threadIdx.x;
    const float* src = R + ((size_t)row << 10);
    float v[4];
    #pragma unroll
    for (int j=0;j<4;j++) v[j] = src[tid + (j<<8)];
    float s = v[0]+v[1]+v[2]+v[3];
    s = blockSum(s, red);
    float mu = s * (1.0f/1024.0f);
    float q = 0.f;
    #pragma unroll
    for (int j=0;j<4;j++) { float d = v[j]-mu; q += d*d; }
    q = blockSum(q, red);
    float inv = rsqrtf(q * (1.0f/1024.0f) + 1e-5f);
    #pragma unroll
    for (int j=0;j<4;j++) {
        int c = tid + (j<<8);
        out[((size_t)row << 10) + c] = (v[j]-mu)*inv*gamma[c] + beta[c];
    }
}

// ---------------- launch -----------------------------------------------------
extern "C" void kernel_launch(void* const* d_in, const int* in_sizes, int n_in,
                              void* d_out, int out_size)
{
    const float* x  = (const float*)d_in[0];
    const int*   ts = (const int*)  d_in[1];
    const float* Wq = (const float*)d_in[2];
    const float* bq = (const float*)d_in[3];
    const float* Wk = (const float*)d_in[4];
    const float* bk = (const float*)d_in[5];
    const float* Wv = (const float*)d_in[6];
    const float* bv = (const float*)d_in[7];
    const float* Wo = (const float*)d_in[8];
    const float* bo = (const float*)d_in[9];
    const float* ga = (const float*)d_in[10];
    const float* be = (const float*)d_in[11];

    float* out1 = (float*)d_out;
    float* out2 = out1 + (size_t)BB*SS*DD;

    void *pq, *pk, *pv, *pvt, *plu, *pctx, *pres, *po2p;
    cudaGetSymbolAddress(&pq,  g_q);
    cudaGetSymbolAddress(&pk,  g_k);
    cudaGetSymbolAddress(&pv,  g_v);
    cudaGetSymbolAddress(&pvt, g_vt);
    cudaGetSymbolAddress(&plu, g_lu);
    cudaGetSymbolAddress(&pctx,g_ctx);
    cudaGetSymbolAddress(&pres,g_res);
    cudaGetSymbolAddress(&po2p,g_o2p);

    const int SM_BIG  = 2*(128+128)*36*4;                 // 73728 B
    const int SM_FLSH = (128 + 2*64 + 2*64)*FST*2;        // 55296 B
    const int SM_O2   = 4*128*FST*2 + 2*64*FST*2 + 512*4; // 94208 B
    cudaFuncSetAttribute((const void*)qkv_gemm,   cudaFuncAttributeMaxDynamicSharedMemorySize, SM_BIG);
    cudaFuncSetAttribute((const void*)oproj_gemm, cudaFuncAttributeMaxDynamicSharedMemorySize, SM_BIG);
    cudaFuncSetAttribute((const void*)flash_pv,   cudaFuncAttributeMaxDynamicSharedMemorySize, SM_FLSH);
    cudaFuncSetAttribute((const void*)out2_part,  cudaFuncAttributeMaxDynamicSharedMemorySize, SM_O2);

    // QKV projections -> bf16 head layout
    qkv_gemm<<<dim3(24,32), 128, SM_BIG>>>(x, Wq, Wk, Wv, bq, bk, bv,
                                           (bf16*)pq, (bf16*)pk, (bf16*)pv);

    // V transpose
    v_transpose<<<dim3(16,BHN), 256>>>((const bf16*)pv, (bf16*)pvt);

    // Flash attention: ctx + unbiased row sums (scores never hit DRAM)
    flash_pv<<<dim3(8,BHN), 256, SM_FLSH>>>((const bf16*)pq, (const bf16*)pk,
                                            (const bf16*)pvt, (float*)pctx,
                                            (float*)plu, ts);

    // out2: recompute scores per head-quad, accumulate unbiased probs
    out2_part<<<dim3(8,4,BB), 256, SM_O2>>>((const bf16*)pq, (const bf16*)pk,
                                            (const float*)plu, (float*)po2p);
    out2_reduce<<<4096, 256>>>((const float*)po2p, out2);

    // out projection + bias + residual
    oproj_gemm<<<dim3(8,32), 128, SM_BIG>>>((const float*)pctx, Wo, bo, x,
                                            (float*)pres);

    // LayerNorm -> output 1
    layernorm<<<dim3(BB*SS), 256>>>((const float*)pres, ga, be, out1);
}

// round 10
// speedup vs baseline: 1.3784x; 1.1858x over previous
#include <cuda_runtime.h>
#include <cuda_bf16.h>
#include <cstdint>
#include <math.h>

#define BB 4
#define SS 1024
#define DD 1024
#define NH 16
#define DKH 64
#define BHN (BB*NH)   // 64
#define FST 72        // smem stride (bf16) for 64-wide tiles
#define SHF 4.0f      // constant softmax shift (cancels exactly in normalization)

typedef __nv_bfloat16 bf16;

// ---------------- device scratch ----------------
__device__ bf16  g_xb[BB*SS*DD];          // x in bf16
__device__ bf16  g_wqb[DD*DD], g_wkb[DD*DD], g_wvb[DD*DD];
__device__ bf16  g_q[BB*NH*SS*DKH];       // [b,h,s,dk], q pre-scaled 0.125
__device__ bf16  g_k[BB*NH*SS*DKH];
__device__ bf16  g_v[BB*NH*SS*DKH];
__device__ bf16  g_vt[BB*NH*DKH*SS];      // V transposed per head: [bh][dk][s]
__device__ float g_lu[BHN*SS];            // unbiased row sums (shifted)
__device__ float g_ctx[BB*SS*DD];
__device__ float g_res[BB*SS*DD];

// ---------------- helpers ----------------
__device__ __forceinline__ float warpSumT(float v){
    #pragma unroll
    for (int o=16;o;o>>=1) v += __shfl_xor_sync(0xffffffffu, v, o);
    return v;
}
__device__ __forceinline__ float blockSum(float v, float* sh){
    v = warpSumT(v);
    int w = threadIdx.x >> 5, l = threadIdx.x & 31;
    if (l == 0) sh[w] = v;
    __syncthreads();
    float r = sh[0];
    #pragma unroll
    for (int i=1;i<8;i++) r += sh[i];
    __syncthreads();
    return r;
}
__device__ __forceinline__ void mma_tf32(float* d, const uint32_t* a, const uint32_t* b){
    asm volatile(
        "mma.sync.aligned.m16n8k8.row.col.f32.tf32.tf32.f32 "
        "{%0,%1,%2,%3}, {%4,%5,%6,%7}, {%8,%9}, {%0,%1,%2,%3};\n"
        : "+f"(d[0]), "+f"(d[1]), "+f"(d[2]), "+f"(d[3])
        : "r"(a[0]), "r"(a[1]), "r"(a[2]), "r"(a[3]),
          "r"(b[0]), "r"(b[1]));
}
__device__ __forceinline__ void mma_bf16(float* d, const uint32_t* a, const uint32_t* b){
    asm volatile(
        "mma.sync.aligned.m16n8k16.row.col.f32.bf16.bf16.f32 "
        "{%0,%1,%2,%3}, {%4,%5,%6,%7}, {%8,%9}, {%0,%1,%2,%3};\n"
        : "+f"(d[0]), "+f"(d[1]), "+f"(d[2]), "+f"(d[3])
        : "r"(a[0]), "r"(a[1]), "r"(a[2]), "r"(a[3]),
          "r"(b[0]), "r"(b[1]));
}
__device__ __forceinline__ void cpasync16(uint32_t s, const void* g){
    asm volatile("cp.async.cg.shared.global [%0], [%1], 16;\n" :: "r"(s), "l"(g));
}
__device__ __forceinline__ uint32_t smem_u32(const void* p){
    return (uint32_t)__cvta_generic_to_shared(p);
}
__device__ __forceinline__ uint32_t pack_bf16x2(float x, float y){
    __nv_bfloat162 a = __floats2bfloat162_rn(x, y);
    return *reinterpret_cast<uint32_t*>(&a);
}

// ---------------- fp32 -> bf16 convert ----------------
__global__ void __launch_bounds__(256)
to_bf16(const float* __restrict__ src, bf16* __restrict__ dst)
{
    int i = (blockIdx.x*256 + threadIdx.x)*4;
    float4 v = *(const float4*)(src + i);
    uint2 u;
    u.x = pack_bf16x2(v.x, v.y);
    u.y = pack_bf16x2(v.z, v.w);
    *(uint2*)(dst + i) = u;
}

// =====================================================================
// Merged QKV projection in bf16 (m16n8k16), bf16 head-layout output.
// =====================================================================
__global__ void __launch_bounds__(128)
qkv_gemm_bf16(const bf16* __restrict__ A,
              const bf16* __restrict__ Wq, const bf16* __restrict__ Wk, const bf16* __restrict__ Wv,
              const float* __restrict__ bq, const float* __restrict__ bk, const float* __restrict__ bv,
              bf16* __restrict__ oq, bf16* __restrict__ ok, bf16* __restrict__ ov)
{
    constexpr int BK=32, SB=40;
    constexpr int MT=4, NTL=8;
    constexpr int Kd=1024;

    __shared__ bf16 As[2][128*SB];
    __shared__ bf16 Bs[2][128*SB];

    const int tid = threadIdx.x;
    const int wsel = blockIdx.x >> 3;
    const int bm0 = blockIdx.y*128, bn0 = (blockIdx.x & 7)*128;

    const bf16* Bg    = (wsel==0) ? Wq : (wsel==1) ? Wk : Wv;
    const float* bias = (wsel==0) ? bq : (wsel==1) ? bk : bv;
    bf16* C           = (wsel==0) ? oq : (wsel==1) ? ok : ov;
    const float scale = (wsel==0) ? 0.125f : 1.0f;

    auto loadA = [&](int buf, int k0){
        #pragma unroll
        for (int i = 0; i < 4; i++){
            int id = tid + i*128;
            int r = id >> 2, c8 = (id & 3)*8;
            cpasync16(smem_u32(&As[buf][r*SB + c8]),
                      A + (size_t)(bm0 + r)*Kd + k0 + c8);
        }
    };
    auto loadB = [&](int buf, int k0){
        #pragma unroll
        for (int i = 0; i < 4; i++){
            int id = tid + i*128;
            int r = id >> 2, c8 = (id & 3)*8;
            cpasync16(smem_u32(&Bs[buf][r*SB + c8]),
                      Bg + (size_t)(bn0 + r)*Kd + k0 + c8);
        }
    };

    const int lane = tid & 31, g = lane >> 2, tg = lane & 3;
    const int warp = tid >> 5;
    const int wm = (warp >> 1) * 64, wn = (warp & 1) * 64;

    float acc[MT][NTL][4];
    #pragma unroll
    for (int i=0;i<MT;i++)
        #pragma unroll
        for (int j=0;j<NTL;j++)
            #pragma unroll
            for (int r=0;r<4;r++) acc[i][j][r] = 0.f;

    loadA(0, 0); loadB(0, 0);
    asm volatile("cp.async.commit_group;\n");

    for (int it = 0; it < Kd/BK; it++){
        int buf = it & 1;
        if (it + 1 < Kd/BK) {
            loadA(buf^1, (it+1)*BK); loadB(buf^1, (it+1)*BK);
            asm volatile("cp.async.commit_group;\n");
            asm volatile("cp.async.wait_group 1;\n");
        } else {
            asm volatile("cp.async.wait_group 0;\n");
        }
        __syncthreads();

        #pragma unroll
        for (int kk = 0; kk < 2; kk++){
            uint32_t af[MT][4], bfr[NTL][2];
            #pragma unroll
            for (int i = 0; i < MT; i++){
                const bf16* ap = &As[buf][(wm + i*16 + g)*SB + kk*16 + 2*tg];
                af[i][0] = *(const uint32_t*)(ap);
                af[i][1] = *(const uint32_t*)(ap + 8*SB);
                af[i][2] = *(const uint32_t*)(ap + 8);
                af[i][3] = *(const uint32_t*)(ap + 8*SB + 8);
            }
            #pragma unroll
            for (int j = 0; j < NTL; j++){
                const bf16* bp = &Bs[buf][(wn + j*8 + g)*SB + kk*16 + 2*tg];
                bfr[j][0] = *(const uint32_t*)(bp);
                bfr[j][1] = *(const uint32_t*)(bp + 8);
            }
            #pragma unroll
            for (int i = 0; i < MT; i++)
                #pragma unroll
                for (int j = 0; j < NTL; j++)
                    mma_bf16(acc[i][j], af[i], bfr[j]);
        }
        __syncthreads();
    }

    #pragma unroll
    for (int i = 0; i < MT; i++){
        #pragma unroll
        for (int rr = 0; rr < 2; rr++){
            int row = bm0 + wm + i*16 + g + rr*8;
            #pragma unroll
            for (int j = 0; j < NTL; j++){
                int col = bn0 + wn + j*8 + 2*tg;
                float vx = (acc[i][j][rr*2+0] + bias[col])   * scale;
                float vy = (acc[i][j][rr*2+1] + bias[col+1]) * scale;
                int b = row >> 10, s = row & 1023;
                int h = col >> 6, dd = col & 63;
                uint32_t u = pack_bf16x2(vx, vy);
                *(uint32_t*)&C[((size_t)(b*NH + h) << 16) + s*DKH + dd] = u;
            }
        }
    }
}

// =====================================================================
// V transpose per head: g_v[bh][s][dk] -> g_vt[bh][dk][s]
// =====================================================================
__global__ void __launch_bounds__(256)
v_transpose(const bf16* __restrict__ V, bf16* __restrict__ Vt)
{
    __shared__ bf16 t[64][FST];
    const int sc = blockIdx.x, bh = blockIdx.y;
    const int tid = threadIdx.x;
    const bf16* src = V + ((size_t)bh << 16) + sc*64*DKH;

    #pragma unroll
    for (int i = 0; i < 2; i++){
        int id = tid + (i << 8);
        int r = id >> 3, c8 = (id & 7) << 3;
        *(uint4*)&t[r][c8] = *(const uint4*)(src + r*DKH + c8);
    }
    __syncthreads();

    bf16* dst = Vt + ((size_t)bh << 16) + sc*64;
    #pragma unroll
    for (int i = 0; i < 2; i++){
        int id = tid + (i << 8);
        int r = id >> 3, c8 = (id & 7) << 3;
        union { uint4 u; bf16 h[8]; } o;
        #pragma unroll
        for (int tj = 0; tj < 8; tj++) o.h[tj] = t[c8 + tj][r];
        *(uint4*)(dst + (size_t)r*SS + c8) = o.u;
    }
}

// =====================================================================
// FLASH: per (mtile=128, bh). S in regs, constant-shift softmax, P@V.
// =====================================================================
__global__ void __launch_bounds__(256)
flash_pv(const bf16* __restrict__ Q, const bf16* __restrict__ K,
         const bf16* __restrict__ Vt, float* __restrict__ ctx,
         float* __restrict__ lu_out, const int* __restrict__ ts_ptr)
{
    extern __shared__ bf16 fsm[];
    bf16* Qs = fsm;                       // 128*FST
    bf16* Ks = fsm + 128*FST;             // 2*64*FST
    bf16* Vs = fsm + 128*FST + 2*64*FST;  // 2*64*FST

    const int tid = threadIdx.x;
    const int lane = tid & 31, g = lane >> 2, tg = lane & 3;
    const int w = tid >> 5;
    const int mt = blockIdx.x, bh = blockIdx.y;
    const int m0 = mt*128;

    const bf16* Qb = Q  + ((size_t)bh << 16) + (size_t)m0*DKH;
    const bf16* Kb = K  + ((size_t)bh << 16);
    const bf16* Vb = Vt + ((size_t)bh << 16);

    #pragma unroll
    for (int i = 0; i < 4; i++){
        int id = tid + (i << 8);
        int r = id >> 3, c8 = (id & 7) << 3;
        cpasync16(smem_u32(&Qs[r*FST + c8]), Qb + r*DKH + c8);
    }
    auto loadK = [&](int buf, int k0){
        #pragma unroll
        for (int i = 0; i < 2; i++){
            int id = tid + (i << 8);
            int r = id >> 3, c8 = (id & 7) << 3;
            cpasync16(smem_u32(&Ks[buf*64*FST + r*FST + c8]),
                      Kb + (size_t)(k0 + r)*DKH + c8);
        }
    };
    auto loadV = [&](int buf, int k0){
        #pragma unroll
        for (int i = 0; i < 2; i++){
            int id = tid + (i << 8);
            int r = id >> 3, c8 = (id & 7) << 3;
            cpasync16(smem_u32(&Vs[buf*64*FST + r*FST + c8]),
                      Vb + (size_t)r*SS + k0 + c8);
        }
    };
    loadK(0, 0); loadV(0, 0);
    asm volatile("cp.async.commit_group;\n");

    float oacc[8][4];
    #pragma unroll
    for (int j=0;j<8;j++)
        #pragma unroll
        for (int v=0;v<4;v++) oacc[j][v]=0.f;
    float l0=0.f, l1=0.f, lu0=0.f, lu1=0.f;

    const bool dob = (ts_ptr[0] < 8) && (mt == 0) && (w < 4);
    const int row0 = m0 + w*16 + g, row1 = row0 + 8;

    uint32_t qf[4][4];
    bool qldd = false;

    for (int c = 0; c < 16; c++){
        int buf = c & 1;
        if (c + 1 < 16){
            loadK(buf^1, (c+1)*64); loadV(buf^1, (c+1)*64);
            asm volatile("cp.async.commit_group;\n");
            asm volatile("cp.async.wait_group 1;\n");
        } else {
            asm volatile("cp.async.wait_group 0;\n");
        }
        __syncthreads();

        if (!qldd){
            #pragma unroll
            for (int kk = 0; kk < 4; kk++){
                const bf16* ap = &Qs[(w*16 + g)*FST + kk*16 + 2*tg];
                qf[kk][0] = *(const uint32_t*)(ap);
                qf[kk][1] = *(const uint32_t*)(ap + 8*FST);
                qf[kk][2] = *(const uint32_t*)(ap + 8);
                qf[kk][3] = *(const uint32_t*)(ap + 8*FST + 8);
            }
            qldd = true;
        }

        const bf16* Kc = Ks + buf*64*FST;
        const bf16* Vc = Vs + buf*64*FST;

        float sacc[8][4];
        #pragma unroll
        for (int j=0;j<8;j++)
            #pragma unroll
            for (int v=0;v<4;v++) sacc[j][v]=0.f;

        #pragma unroll
        for (int kk = 0; kk < 4; kk++){
            #pragma unroll
            for (int j = 0; j < 8; j++){
                const bf16* bp = &Kc[(j*8 + g)*FST + kk*16 + 2*tg];
                uint32_t bfr[2] = { *(const uint32_t*)(bp), *(const uint32_t*)(bp + 8) };
                mma_bf16(sacc[j], qf[kk], bfr);
            }
        }

        const bool bchunk = dob && (c == 0);
        if (bchunk){
            float u0=0.f, u1=0.f;
            #pragma unroll
            for (int j = 0; j < 8; j++){
                u0 += __expf(sacc[j][0]-SHF) + __expf(sacc[j][1]-SHF);
                u1 += __expf(sacc[j][2]-SHF) + __expf(sacc[j][3]-SHF);
            }
            lu0 += u0; lu1 += u1;
            #pragma unroll
            for (int j = 0; j < 8; j++){
                int col = j*8 + 2*tg;
                sacc[j][0] += 0.1f / (fabsf((float)(row0 - col))     + 1.0f);
                sacc[j][1] += 0.1f / (fabsf((float)(row0 - col - 1)) + 1.0f);
                sacc[j][2] += 0.1f / (fabsf((float)(row1 - col))     + 1.0f);
                sacc[j][3] += 0.1f / (fabsf((float)(row1 - col - 1)) + 1.0f);
            }
        }

        uint32_t pk0[8], pk1[8];
        float r0=0.f, r1=0.f;
        #pragma unroll
        for (int j = 0; j < 8; j++){
            float p0 = __expf(sacc[j][0]-SHF), p1 = __expf(sacc[j][1]-SHF);
            float p2 = __expf(sacc[j][2]-SHF), p3 = __expf(sacc[j][3]-SHF);
            r0 += p0 + p1; r1 += p2 + p3;
            pk0[j] = pack_bf16x2(p0, p1);
            pk1[j] = pack_bf16x2(p2, p3);
        }
        l0 += r0; l1 += r1;
        if (!bchunk){ lu0 += r0; lu1 += r1; }

        #pragma unroll
        for (int kk = 0; kk < 4; kk++){
            uint32_t a[4] = { pk0[2*kk], pk1[2*kk], pk0[2*kk+1], pk1[2*kk+1] };
            #pragma unroll
            for (int j = 0; j < 8; j++){
                const bf16* bp = &Vc[(j*8 + g)*FST + kk*16 + 2*tg];
                uint32_t b2[2] = { *(const uint32_t*)(bp), *(const uint32_t*)(bp + 8) };
                mma_bf16(oacc[j], a, b2);
            }
        }
        __syncthreads();
    }

    #pragma unroll
    for (int o = 1; o < 4; o <<= 1){
        l0  += __shfl_xor_sync(0xffffffffu, l0,  o);
        l1  += __shfl_xor_sync(0xffffffffu, l1,  o);
        lu0 += __shfl_xor_sync(0xffffffffu, lu0, o);
        lu1 += __shfl_xor_sync(0xffffffffu, lu1, o);
    }
    float i0 = 1.0f / l0, i1 = 1.0f / l1;

    float* cb = ctx + ((size_t)(bh >> 4) << 20) + (size_t)(bh & 15)*64;
    #pragma unroll
    for (int j = 0; j < 8; j++){
        int col = j*8 + 2*tg;
        *(float2*)&cb[(size_t)row0*DD + col] = make_float2(oacc[j][0]*i0, oacc[j][1]*i0);
        *(float2*)&cb[(size_t)row1*DD + col] = make_float2(oacc[j][2]*i1, oacc[j][3]*i1);
    }
    if (tg == 0){
        lu_out[bh*SS + row0] = lu0;
        lu_out[bh*SS + row1] = lu1;
    }
}

// =====================================================================
// out2 DIRECT: block (mt, nc, b) owns out2[b][mt*128..][nc*128..]; loops
// all 16 heads, S recomputed by MMA, exp(s-SHF)/lu accumulated in fp32.
// grid (8, 8, 4) = 256 blocks, 256 threads. No partials, no reduce.
// =====================================================================
__global__ void __launch_bounds__(256)
out2_direct(const bf16* __restrict__ Q, const bf16* __restrict__ K,
            const float* __restrict__ lu, float* __restrict__ out2)
{
    extern __shared__ bf16 o2sm[];
    bf16* Qs = o2sm;                // [2][128*FST]
    bf16* Ks = o2sm + 2*128*FST;    // [2][128*FST]

    const int tid = threadIdx.x;
    const int lane = tid & 31, g = lane >> 2, tg = lane & 3;
    const int w = tid >> 5;
    const int mt = blockIdx.x, nc = blockIdx.y, b = blockIdx.z;
    const int m0 = mt*128, n0 = nc*128;

    // FIXED loader: 128 rows x 64 cols bf16 = 128*8 = 1024 16B chunks each
    // for Q and K -> 4 iterations x 256 threads, r = id>>3, c8 = (id&7)*8.
    auto loadQK = [&](int buf, int hi){
        const bf16* qsrc = Q + ((size_t)(b*NH + hi) << 16) + (size_t)m0*DKH;
        const bf16* ksrc = K + ((size_t)(b*NH + hi) << 16) + (size_t)n0*DKH;
        #pragma unroll
        for (int i = 0; i < 4; i++){
            int id = tid + (i << 8);
            int r = id >> 3, c8 = (id & 7) << 3;
            cpasync16(smem_u32(&Qs[buf*128*FST + r*FST + c8]), qsrc + (size_t)r*DKH + c8);
            cpasync16(smem_u32(&Ks[buf*128*FST + r*FST + c8]), ksrc + (size_t)r*DKH + c8);
        }
    };
    loadQK(0, 0);
    asm volatile("cp.async.commit_group;\n");

    float acc[2][8][4];
    #pragma unroll
    for (int h2=0;h2<2;h2++)
        #pragma unroll
        for (int j=0;j<8;j++)
            #pragma unroll
            for (int v=0;v<4;v++) acc[h2][j][v]=0.f;

    const int row0 = m0 + w*16 + g, row1 = row0 + 8;

    for (int hi = 0; hi < NH; hi++){
        int buf = hi & 1;
        if (hi + 1 < NH){
            loadQK(buf^1, hi+1);
            asm volatile("cp.async.commit_group;\n");
            asm volatile("cp.async.wait_group 1;\n");
        } else {
            asm volatile("cp.async.wait_group 0;\n");
        }
        __syncthreads();

        float li0 = 1.0f / lu[(b*NH + hi)*SS + row0];
        float li1 = 1.0f / lu[(b*NH + hi)*SS + row1];

        uint32_t qf[4][4];
        const bf16* qb = Qs + buf*128*FST;
        #pragma unroll
        for (int kk = 0; kk < 4; kk++){
            const bf16* ap = &qb[(w*16 + g)*FST + kk*16 + 2*tg];
            qf[kk][0] = *(const uint32_t*)(ap);
            qf[kk][1] = *(const uint32_t*)(ap + 8*FST);
            qf[kk][2] = *(const uint32_t*)(ap + 8);
            qf[kk][3] = *(const uint32_t*)(ap + 8*FST + 8);
        }

        const bf16* Kc = Ks + buf*128*FST;
        #pragma unroll
        for (int half = 0; half < 2; half++){
            float sacc[8][4];
            #pragma unroll
            for (int j=0;j<8;j++)
                #pragma unroll
                for (int v=0;v<4;v++) sacc[j][v]=0.f;

            #pragma unroll
            for (int kk = 0; kk < 4; kk++){
                #pragma unroll
                for (int j = 0; j < 8; j++){
                    const bf16* bp = &Kc[(half*64 + j*8 + g)*FST + kk*16 + 2*tg];
                    uint32_t bfr[2] = { *(const uint32_t*)(bp), *(const uint32_t*)(bp + 8) };
                    mma_bf16(sacc[j], qf[kk], bfr);
                }
            }
            #pragma unroll
            for (int j = 0; j < 8; j++){
                acc[half][j][0] += __expf(sacc[j][0]-SHF)*li0;
                acc[half][j][1] += __expf(sacc[j][1]-SHF)*li0;
                acc[half][j][2] += __expf(sacc[j][2]-SHF)*li1;
                acc[half][j][3] += __expf(sacc[j][3]-SHF)*li1;
            }
        }
        __syncthreads();
    }

    const float k16 = 1.0f/16.0f;
    float* ob = out2 + ((size_t)b << 20);
    #pragma unroll
    for (int half = 0; half < 2; half++){
        #pragma unroll
        for (int j = 0; j < 8; j++){
            int col = n0 + half*64 + j*8 + 2*tg;
            *(float2*)&ob[(size_t)row0*SS + col] =
                make_float2(acc[half][j][0]*k16, acc[half][j][1]*k16);
            *(float2*)&ob[(size_t)row1*SS + col] =
                make_float2(acc[half][j][2]*k16, acc[half][j][3]*k16);
        }
    }
}

// =====================================================================
// Out-projection (tf32): fp32 out, + bias + residual
// =====================================================================
__global__ void __launch_bounds__(128)
oproj_gemm(const float* __restrict__ A, const float* __restrict__ Bg,
           const float* __restrict__ bias, const float* __restrict__ resid,
           float* __restrict__ C)
{
    constexpr int BM=128, BN=128, BK=32, S=36;
    constexpr int T=128, MT=4, NTL=8;
    constexpr int Kd=1024, Nd=1024;

    extern __shared__ float sm[];
    float* As = sm;
    float* Bs = sm + 2*BM*S;

    const int tid = threadIdx.x;
    const int bm0 = blockIdx.y*BM, bn0 = blockIdx.x*BN;

    auto loadA = [&](int buf, int k0){
        #pragma unroll
        for (int i = 0; i < 8; i++){
            int id = tid + i*T;
            int r = id >> 3, ks = (id & 7)*4;
            cpasync16(smem_u32(&As[buf*BM*S + r*S + ks]),
                      A + (size_t)(bm0 + r)*Kd + k0 + ks);
        }
    };
    auto loadB = [&](int buf, int k0){
        #pragma unroll
        for (int i = 0; i < 8; i++){
            int id = tid + i*T;
            int r = id >> 3, ks = (id & 7)*4;
            cpasync16(smem_u32(&Bs[buf*BN*S + r*S + ks]),
                      Bg + (size_t)(bn0 + r)*Kd + k0 + ks);
        }
    };

    const int lane = tid & 31, g = lane >> 2, tg = lane & 3;
    const int warp = tid >> 5;
    const int wm = (warp >> 1) * 64, wn = (warp & 1) * 64;

    float acc[MT][NTL][4];
    #pragma unroll
    for (int i=0;i<MT;i++)
        #pragma unroll
        for (int j=0;j<NTL;j++)
            #pragma unroll
            for (int r=0;r<4;r++) acc[i][j][r] = 0.f;

    loadA(0, 0); loadB(0, 0);
    asm volatile("cp.async.commit_group;\n");

    for (int it = 0; it < Kd/BK; it++){
        int buf = it & 1;
        if (it + 1 < Kd/BK) {
            loadA(buf^1, (it+1)*BK); loadB(buf^1, (it+1)*BK);
            asm volatile("cp.async.commit_group;\n");
            asm volatile("cp.async.wait_group 1;\n");
        } else {
            asm volatile("cp.async.wait_group 0;\n");
        }
        __syncthreads();

        const float* Ab = As + buf*BM*S;
        const float* Bb = Bs + buf*BN*S;
        #pragma unroll
        for (int c = 0; c < BK/8; c++){
            uint32_t af[MT][4], bf[NTL][2];
            #pragma unroll
            for (int i = 0; i < MT; i++){
                const float* ap = Ab + (wm + i*16 + g)*S + c*8 + tg;
                af[i][0] = __float_as_uint(ap[0]);
                af[i][1] = __float_as_uint(ap[8*S]);
                af[i][2] = __float_as_uint(ap[4]);
                af[i][3] = __float_as_uint(ap[8*S + 4]);
            }
            #pragma unroll
            for (int j = 0; j < NTL; j++){
                const float* bp = Bb + (wn + j*8 + g)*S + c*8 + tg;
                bf[j][0] = __float_as_uint(bp[0]);
                bf[j][1] = __float_as_uint(bp[4]);
            }
            #pragma unroll
            for (int i = 0; i < MT; i++)
                #pragma unroll
                for (int j = 0; j < NTL; j++)
                    mma_tf32(acc[i][j], af[i], bf[j]);
        }
        __syncthreads();
    }

    #pragma unroll
    for (int i = 0; i < MT; i++){
        #pragma unroll
        for (int rr = 0; rr < 2; rr++){
            int row = bm0 + wm + i*16 + g + rr*8;
            #pragma unroll
            for (int j = 0; j < NTL; j++){
                int col = bn0 + wn + j*8 + 2*tg;
                size_t idx = (size_t)row*Nd + col;
                float2 r2 = *(const float2*)&resid[idx];
                float2 o = make_float2(acc[i][j][rr*2+0] + bias[col] + r2.x,
                                       acc[i][j][rr*2+1] + bias[col+1] + r2.y);
                *(float2*)&C[idx] = o;
            }
        }
    }
}

// ---------------- LayerNorm --------------------------------------------------
__global__ void __launch_bounds__(256)
layernorm(const float* __restrict__ R, const float* __restrict__ gamma,
          const float* __restrict__ beta, float* __restrict__ out)
{
    __shared__ float red[8];
    int row = blockIdx.x;
    int tid = threadIdx.x;
    const float* src = R + ((size_t)row << 10);
    float v[4];
    #pragma unroll
    for (int j=0;j<4;j++) v[j] = src[tid + (j<<8)];
    float s = v[0]+v[1]+v[2]+v[3];
    s = blockSum(s, red);
    float mu = s * (1.0f/1024.0f);
    float q = 0.f;
    #pragma unroll
    for (int j=0;j<4;j++) { float d = v[j]-mu; q += d*d; }
    q = blockSum(q, red);
    float inv = rsqrtf(q * (1.0f/1024.0f) + 1e-5f);
    #pragma unroll
    for (int j=0;j<4;j++) {
        int c = tid + (j<<8);
        out[((size_t)row << 10) + c] = (v[j]-mu)*inv*gamma[c] + beta[c];
    }
}

// ---------------- launch -----------------------------------------------------
extern "C" void kernel_launch(void* const* d_in, const int* in_sizes, int n_in,
                              void* d_out, int out_size)
{
    const float* x  = (const float*)d_in[0];
    const int*   ts = (const int*)  d_in[1];
    const float* Wq = (const float*)d_in[2];
    const float* bq = (const float*)d_in[3];
    const float* Wk = (const float*)d_in[4];
    const float* bk = (const float*)d_in[5];
    const float* Wv = (const float*)d_in[6];
    const float* bv = (const float*)d_in[7];
    const float* Wo = (const float*)d_in[8];
    const float* bo = (const float*)d_in[9];
    const float* ga = (const float*)d_in[10];
    const float* be = (const float*)d_in[11];

    float* out1 = (float*)d_out;
    float* out2 = out1 + (size_t)BB*SS*DD;

    void *pxb, *pwq, *pwk, *pwv, *pq, *pk, *pv, *pvt, *plu, *pctx, *pres;
    cudaGetSymbolAddress(&pxb, g_xb);
    cudaGetSymbolAddress(&pwq, g_wqb);
    cudaGetSymbolAddress(&pwk, g_wkb);
    cudaGetSymbolAddress(&pwv, g_wvb);
    cudaGetSymbolAddress(&pq,  g_q);
    cudaGetSymbolAddress(&pk,  g_k);
    cudaGetSymbolAddress(&pv,  g_v);
    cudaGetSymbolAddress(&pvt, g_vt);
    cudaGetSymbolAddress(&plu, g_lu);
    cudaGetSymbolAddress(&pctx,g_ctx);
    cudaGetSymbolAddress(&pres,g_res);

    const int SM_BIG  = 2*(128+128)*36*4;                 // 73728 B
    const int SM_FLSH = (128 + 2*64 + 2*64)*FST*2;        // 55296 B
    const int SM_O2   = 4*128*FST*2;                      // 73728 B
    cudaFuncSetAttribute((const void*)oproj_gemm,  cudaFuncAttributeMaxDynamicSharedMemorySize, SM_BIG);
    cudaFuncSetAttribute((const void*)flash_pv,    cudaFuncAttributeMaxDynamicSharedMemorySize, SM_FLSH);
    cudaFuncSetAttribute((const void*)out2_direct, cudaFuncAttributeMaxDynamicSharedMemorySize, SM_O2);

    // bf16 copies of x and projection weights
    to_bf16<<<4096, 256>>>(x,  (bf16*)pxb);
    to_bf16<<<1024, 256>>>(Wq, (bf16*)pwq);
    to_bf16<<<1024, 256>>>(Wk, (bf16*)pwk);
    to_bf16<<<1024, 256>>>(Wv, (bf16*)pwv);

    // QKV projections (bf16 MMA) -> bf16 head layout
    qkv_gemm_bf16<<<dim3(24,32), 128>>>((const bf16*)pxb,
                                        (const bf16*)pwq, (const bf16*)pwk, (const bf16*)pwv,
                                        bq, bk, bv,
                                        (bf16*)pq, (bf16*)pk, (bf16*)pv);

    // V transpose
    v_transpose<<<dim3(16,BHN), 256>>>((const bf16*)pv, (bf16*)pvt);

    // Flash attention: ctx + unbiased row sums
    flash_pv<<<dim3(8,BHN), 256, SM_FLSH>>>((const bf16*)pq, (const bf16*)pk,
                                            (const bf16*)pvt, (float*)pctx,
                                            (float*)plu, ts);

    // out2 computed directly (no partials)
    out2_direct<<<dim3(8,8,BB), 256, SM_O2>>>((const bf16*)pq, (const bf16*)pk,
                                              (const float*)plu, out2);

    // out projection + bias + residual
    oproj_gemm<<<dim3(8,32), 128, SM_BIG>>>((const float*)pctx, Wo, bo, x,
                                            (float*)pres);

    // LayerNorm -> output 1
    layernorm<<<dim3(BB*SS), 256>>>((const float*)pres, ga, be, out1);
}

// round 11
// speedup vs baseline: 1.4954x; 1.0848x over previous
#include <cuda_runtime.h>
#include <cuda_bf16.h>
#include <cstdint>
#include <math.h>

#define BB 4
#define SS 1024
#define DD 1024
#define NH 16
#define DKH 64
#define BHN (BB*NH)   // 64
#define FST 72        // smem stride (bf16) for 64-wide tiles
#define SHF 4.0f      // constant softmax shift (cancels exactly in normalization)

typedef __nv_bfloat16 bf16;

// ---------------- device scratch ----------------
__device__ bf16  g_xb[BB*SS*DD];          // x in bf16
__device__ bf16  g_wqb[DD*DD], g_wkb[DD*DD], g_wvb[DD*DD], g_wob[DD*DD];
__device__ bf16  g_q[BB*NH*SS*DKH];       // [b,h,s,dk], q pre-scaled 0.125
__device__ bf16  g_k[BB*NH*SS*DKH];
__device__ bf16  g_v[BB*NH*SS*DKH];
__device__ bf16  g_vt[BB*NH*DKH*SS];      // V transposed per head: [bh][dk][s]
__device__ float g_lu[BHN*SS];            // unbiased row sums (shifted)
__device__ bf16  g_ctxb[BB*SS*DD];        // ctx in bf16
__device__ float g_res[BB*SS*DD];

// ---------------- helpers ----------------
__device__ __forceinline__ float warpSumT(float v){
    #pragma unroll
    for (int o=16;o;o>>=1) v += __shfl_xor_sync(0xffffffffu, v, o);
    return v;
}
__device__ __forceinline__ float blockSum(float v, float* sh){
    v = warpSumT(v);
    int w = threadIdx.x >> 5, l = threadIdx.x & 31;
    if (l == 0) sh[w] = v;
    __syncthreads();
    float r = sh[0];
    #pragma unroll
    for (int i=1;i<8;i++) r += sh[i];
    __syncthreads();
    return r;
}
__device__ __forceinline__ void mma_bf16(float* d, const uint32_t* a, const uint32_t* b){
    asm volatile(
        "mma.sync.aligned.m16n8k16.row.col.f32.bf16.bf16.f32 "
        "{%0,%1,%2,%3}, {%4,%5,%6,%7}, {%8,%9}, {%0,%1,%2,%3};\n"
        : "+f"(d[0]), "+f"(d[1]), "+f"(d[2]), "+f"(d[3])
        : "r"(a[0]), "r"(a[1]), "r"(a[2]), "r"(a[3]),
          "r"(b[0]), "r"(b[1]));
}
__device__ __forceinline__ void cpasync16(uint32_t s, const void* g){
    asm volatile("cp.async.cg.shared.global [%0], [%1], 16;\n" :: "r"(s), "l"(g));
}
__device__ __forceinline__ uint32_t smem_u32(const void* p){
    return (uint32_t)__cvta_generic_to_shared(p);
}
__device__ __forceinline__ uint32_t pack_bf16x2(float x, float y){
    __nv_bfloat162 a = __floats2bfloat162_rn(x, y);
    return *reinterpret_cast<uint32_t*>(&a);
}

// ---------------- fused fp32 -> bf16 convert for all 5 tensors ------------
// blocks 0..4095 -> x (4M), 4096..5119 -> Wq, +1024 each -> Wk, Wv, Wo.
__global__ void __launch_bounds__(256)
to_bf16_all(const float* __restrict__ x,
            const float* __restrict__ Wq, const float* __restrict__ Wk,
            const float* __restrict__ Wv, const float* __restrict__ Wo,
            bf16* __restrict__ xb, bf16* __restrict__ wqb, bf16* __restrict__ wkb,
            bf16* __restrict__ wvb, bf16* __restrict__ wob)
{
    int bidx = blockIdx.x;
    const float* src; bf16* dst; int base;
    if      (bidx < 4096){ src = x;  dst = xb;  base = bidx; }
    else if (bidx < 5120){ src = Wq; dst = wqb; base = bidx - 4096; }
    else if (bidx < 6144){ src = Wk; dst = wkb; base = bidx - 5120; }
    else if (bidx < 7168){ src = Wv; dst = wvb; base = bidx - 6144; }
    else                 { src = Wo; dst = wob; base = bidx - 7168; }
    int i = (base*256 + threadIdx.x)*4;
    float4 v = *(const float4*)(src + i);
    uint2 u;
    u.x = pack_bf16x2(v.x, v.y);
    u.y = pack_bf16x2(v.z, v.w);
    *(uint2*)(dst + i) = u;
}

// =====================================================================
// bf16 GEMM core (m16n8k16): A[M,1024] bf16 row-major, B[N,1024] bf16
// row-major (NT). 128 threads, 128x128 block tile, 64x64 warp tiles.
//  MODE 0: QKV merged -> bf16 head-layout + (acc+bias)*scale
//  MODE 1: out-projection -> fp32 + bias + residual
// =====================================================================
template<int MODE>
__global__ void __launch_bounds__(128)
gemm_bf16(const bf16* __restrict__ A,
          const bf16* __restrict__ W0, const bf16* __restrict__ W1, const bf16* __restrict__ W2,
          const float* __restrict__ b0, const float* __restrict__ b1, const float* __restrict__ b2,
          const float* __restrict__ resid,
          void* __restrict__ o0, void* __restrict__ o1, void* __restrict__ o2)
{
    constexpr int BK=32, SB=40;
    constexpr int MT=4, NTL=8;
    constexpr int Kd=1024;

    __shared__ bf16 As[2][128*SB];
    __shared__ bf16 Bs[2][128*SB];

    const int tid = threadIdx.x;
    const int wsel = (MODE == 0) ? (blockIdx.x >> 3) : 0;
    const int bm0 = blockIdx.y*128;
    const int bn0 = (MODE == 0) ? (blockIdx.x & 7)*128 : blockIdx.x*128;

    const bf16* Bg    = (wsel==0) ? W0 : (wsel==1) ? W1 : W2;
    const float* bias = (wsel==0) ? b0 : (wsel==1) ? b1 : b2;
    void* C           = (wsel==0) ? o0 : (wsel==1) ? o1 : o2;
    const float scale = (MODE==0 && wsel==0) ? 0.125f : 1.0f;

    auto loadA = [&](int buf, int k0){
        #pragma unroll
        for (int i = 0; i < 4; i++){
            int id = tid + i*128;
            int r = id >> 2, c8 = (id & 3)*8;
            cpasync16(smem_u32(&As[buf][r*SB + c8]),
                      A + (size_t)(bm0 + r)*Kd + k0 + c8);
        }
    };
    auto loadB = [&](int buf, int k0){
        #pragma unroll
        for (int i = 0; i < 4; i++){
            int id = tid + i*128;
            int r = id >> 2, c8 = (id & 3)*8;
            cpasync16(smem_u32(&Bs[buf][r*SB + c8]),
                      Bg + (size_t)(bn0 + r)*Kd + k0 + c8);
        }
    };

    const int lane = tid & 31, g = lane >> 2, tg = lane & 3;
    const int warp = tid >> 5;
    const int wm = (warp >> 1) * 64, wn = (warp & 1) * 64;

    float acc[MT][NTL][4];
    #pragma unroll
    for (int i=0;i<MT;i++)
        #pragma unroll
        for (int j=0;j<NTL;j++)
            #pragma unroll
            for (int r=0;r<4;r++) acc[i][j][r] = 0.f;

    loadA(0, 0); loadB(0, 0);
    asm volatile("cp.async.commit_group;\n");

    for (int it = 0; it < Kd/BK; it++){
        int buf = it & 1;
        if (it + 1 < Kd/BK) {
            loadA(buf^1, (it+1)*BK); loadB(buf^1, (it+1)*BK);
            asm volatile("cp.async.commit_group;\n");
            asm volatile("cp.async.wait_group 1;\n");
        } else {
            asm volatile("cp.async.wait_group 0;\n");
        }
        __syncthreads();

        #pragma unroll
        for (int kk = 0; kk < 2; kk++){
            uint32_t af[MT][4], bfr[NTL][2];
            #pragma unroll
            for (int i = 0; i < MT; i++){
                const bf16* ap = &As[buf][(wm + i*16 + g)*SB + kk*16 + 2*tg];
                af[i][0] = *(const uint32_t*)(ap);
                af[i][1] = *(const uint32_t*)(ap + 8*SB);
                af[i][2] = *(const uint32_t*)(ap + 8);
                af[i][3] = *(const uint32_t*)(ap + 8*SB + 8);
            }
            #pragma unroll
            for (int j = 0; j < NTL; j++){
                const bf16* bp = &Bs[buf][(wn + j*8 + g)*SB + kk*16 + 2*tg];
                bfr[j][0] = *(const uint32_t*)(bp);
                bfr[j][1] = *(const uint32_t*)(bp + 8);
            }
            #pragma unroll
            for (int i = 0; i < MT; i++)
                #pragma unroll
                for (int j = 0; j < NTL; j++)
                    mma_bf16(acc[i][j], af[i], bfr[j]);
        }
        __syncthreads();
    }

    #pragma unroll
    for (int i = 0; i < MT; i++){
        #pragma unroll
        for (int rr = 0; rr < 2; rr++){
            int row = bm0 + wm + i*16 + g + rr*8;
            #pragma unroll
            for (int j = 0; j < NTL; j++){
                int col = bn0 + wn + j*8 + 2*tg;
                float vx = acc[i][j][rr*2+0] + bias[col];
                float vy = acc[i][j][rr*2+1] + bias[col+1];
                if (MODE == 0){
                    vx *= scale; vy *= scale;
                    int b = row >> 10, s = row & 1023;
                    int h = col >> 6, dd = col & 63;
                    uint32_t u = pack_bf16x2(vx, vy);
                    *(uint32_t*)&((bf16*)C)[((size_t)(b*NH + h) << 16) + s*DKH + dd] = u;
                } else {
                    size_t idx = (size_t)row*DD + col;
                    float2 r2 = *(const float2*)&resid[idx];
                    float2 o = make_float2(vx + r2.x, vy + r2.y);
                    *(float2*)&((float*)C)[idx] = o;
                }
            }
        }
    }
}

// =====================================================================
// V transpose per head: g_v[bh][s][dk] -> g_vt[bh][dk][s]
// =====================================================================
__global__ void __launch_bounds__(256)
v_transpose(const bf16* __restrict__ V, bf16* __restrict__ Vt)
{
    __shared__ bf16 t[64][FST];
    const int sc = blockIdx.x, bh = blockIdx.y;
    const int tid = threadIdx.x;
    const bf16* src = V + ((size_t)bh << 16) + sc*64*DKH;

    #pragma unroll
    for (int i = 0; i < 2; i++){
        int id = tid + (i << 8);
        int r = id >> 3, c8 = (id & 7) << 3;
        *(uint4*)&t[r][c8] = *(const uint4*)(src + r*DKH + c8);
    }
    __syncthreads();

    bf16* dst = Vt + ((size_t)bh << 16) + sc*64;
    #pragma unroll
    for (int i = 0; i < 2; i++){
        int id = tid + (i << 8);
        int r = id >> 3, c8 = (id & 7) << 3;
        union { uint4 u; bf16 h[8]; } o;
        #pragma unroll
        for (int tj = 0; tj < 8; tj++) o.h[tj] = t[c8 + tj][r];
        *(uint4*)(dst + (size_t)r*SS + c8) = o.u;
    }
}

// =====================================================================
// FLASH: per (mtile=128, bh). S in regs, constant-shift softmax, P@V.
// ctx written in bf16.
// =====================================================================
__global__ void __launch_bounds__(256)
flash_pv(const bf16* __restrict__ Q, const bf16* __restrict__ K,
         const bf16* __restrict__ Vt, bf16* __restrict__ ctx,
         float* __restrict__ lu_out, const int* __restrict__ ts_ptr)
{
    extern __shared__ bf16 fsm[];
    bf16* Qs = fsm;                       // 128*FST
    bf16* Ks = fsm + 128*FST;             // 2*64*FST
    bf16* Vs = fsm + 128*FST + 2*64*FST;  // 2*64*FST

    const int tid = threadIdx.x;
    const int lane = tid & 31, g = lane >> 2, tg = lane & 3;
    const int w = tid >> 5;
    const int mt = blockIdx.x, bh = blockIdx.y;
    const int m0 = mt*128;

    const bf16* Qb = Q  + ((size_t)bh << 16) + (size_t)m0*DKH;
    const bf16* Kb = K  + ((size_t)bh << 16);
    const bf16* Vb = Vt + ((size_t)bh << 16);

    #pragma unroll
    for (int i = 0; i < 4; i++){
        int id = tid + (i << 8);
        int r = id >> 3, c8 = (id & 7) << 3;
        cpasync16(smem_u32(&Qs[r*FST + c8]), Qb + r*DKH + c8);
    }
    auto loadK = [&](int buf, int k0){
        #pragma unroll
        for (int i = 0; i < 2; i++){
            int id = tid + (i << 8);
            int r = id >> 3, c8 = (id & 7) << 3;
            cpasync16(smem_u32(&Ks[buf*64*FST + r*FST + c8]),
                      Kb + (size_t)(k0 + r)*DKH + c8);
        }
    };
    auto loadV = [&](int buf, int k0){
        #pragma unroll
        for (int i = 0; i < 2; i++){
            int id = tid + (i << 8);
            int r = id >> 3, c8 = (id & 7) << 3;
            cpasync16(smem_u32(&Vs[buf*64*FST + r*FST + c8]),
                      Vb + (size_t)r*SS + k0 + c8);
        }
    };
    loadK(0, 0); loadV(0, 0);
    asm volatile("cp.async.commit_group;\n");

    float oacc[8][4];
    #pragma unroll
    for (int j=0;j<8;j++)
        #pragma unroll
        for (int v=0;v<4;v++) oacc[j][v]=0.f;
    float l0=0.f, l1=0.f, lu0=0.f, lu1=0.f;

    const bool dob = (ts_ptr[0] < 8) && (mt == 0) && (w < 4);
    const int row0 = m0 + w*16 + g, row1 = row0 + 8;

    uint32_t qf[4][4];
    bool qldd = false;

    for (int c = 0; c < 16; c++){
        int buf = c & 1;
        if (c + 1 < 16){
            loadK(buf^1, (c+1)*64); loadV(buf^1, (c+1)*64);
            asm volatile("cp.async.commit_group;\n");
            asm volatile("cp.async.wait_group 1;\n");
        } else {
            asm volatile("cp.async.wait_group 0;\n");
        }
        __syncthreads();

        if (!qldd){
            #pragma unroll
            for (int kk = 0; kk < 4; kk++){
                const bf16* ap = &Qs[(w*16 + g)*FST + kk*16 + 2*tg];
                qf[kk][0] = *(const uint32_t*)(ap);
                qf[kk][1] = *(const uint32_t*)(ap + 8*FST);
                qf[kk][2] = *(const uint32_t*)(ap + 8);
                qf[kk][3] = *(const uint32_t*)(ap + 8*FST + 8);
            }
            qldd = true;
        }

        const bf16* Kc = Ks + buf*64*FST;
        const bf16* Vc = Vs + buf*64*FST;

        float sacc[8][4];
        #pragma unroll
        for (int j=0;j<8;j++)
            #pragma unroll
            for (int v=0;v<4;v++) sacc[j][v]=0.f;

        #pragma unroll
        for (int kk = 0; kk < 4; kk++){
            #pragma unroll
            for (int j = 0; j < 8; j++){
                const bf16* bp = &Kc[(j*8 + g)*FST + kk*16 + 2*tg];
                uint32_t bfr[2] = { *(const uint32_t*)(bp), *(const uint32_t*)(bp + 8) };
                mma_bf16(sacc[j], qf[kk], bfr);
            }
        }

        const bool bchunk = dob && (c == 0);
        if (bchunk){
            float u0=0.f, u1=0.f;
            #pragma unroll
            for (int j = 0; j < 8; j++){
                u0 += __expf(sacc[j][0]-SHF) + __expf(sacc[j][1]-SHF);
                u1 += __expf(sacc[j][2]-SHF) + __expf(sacc[j][3]-SHF);
            }
            lu0 += u0; lu1 += u1;
            #pragma unroll
            for (int j = 0; j < 8; j++){
                int col = j*8 + 2*tg;
                sacc[j][0] += 0.1f / (fabsf((float)(row0 - col))     + 1.0f);
                sacc[j][1] += 0.1f / (fabsf((float)(row0 - col - 1)) + 1.0f);
                sacc[j][2] += 0.1f / (fabsf((float)(row1 - col))     + 1.0f);
                sacc[j][3] += 0.1f / (fabsf((float)(row1 - col - 1)) + 1.0f);
            }
        }

        uint32_t pk0[8], pk1[8];
        float r0=0.f, r1=0.f;
        #pragma unroll
        for (int j = 0; j < 8; j++){
            float p0 = __expf(sacc[j][0]-SHF), p1 = __expf(sacc[j][1]-SHF);
            float p2 = __expf(sacc[j][2]-SHF), p3 = __expf(sacc[j][3]-SHF);
            r0 += p0 + p1; r1 += p2 + p3;
            pk0[j] = pack_bf16x2(p0, p1);
            pk1[j] = pack_bf16x2(p2, p3);
        }
        l0 += r0; l1 += r1;
        if (!bchunk){ lu0 += r0; lu1 += r1; }

        #pragma unroll
        for (int kk = 0; kk < 4; kk++){
            uint32_t a[4] = { pk0[2*kk], pk1[2*kk], pk0[2*kk+1], pk1[2*kk+1] };
            #pragma unroll
            for (int j = 0; j < 8; j++){
                const bf16* bp = &Vc[(j*8 + g)*FST + kk*16 + 2*tg];
                uint32_t b2[2] = { *(const uint32_t*)(bp), *(const uint32_t*)(bp + 8) };
                mma_bf16(oacc[j], a, b2);
            }
        }
        __syncthreads();
    }

    #pragma unroll
    for (int o = 1; o < 4; o <<= 1){
        l0  += __shfl_xor_sync(0xffffffffu, l0,  o);
        l1  += __shfl_xor_sync(0xffffffffu, l1,  o);
        lu0 += __shfl_xor_sync(0xffffffffu, lu0, o);
        lu1 += __shfl_xor_sync(0xffffffffu, lu1, o);
    }
    float i0 = 1.0f / l0, i1 = 1.0f / l1;

    bf16* cb = ctx + ((size_t)(bh >> 4) << 20) + (size_t)(bh & 15)*64;
    #pragma unroll
    for (int j = 0; j < 8; j++){
        int col = j*8 + 2*tg;
        *(uint32_t*)&cb[(size_t)row0*DD + col] = pack_bf16x2(oacc[j][0]*i0, oacc[j][1]*i0);
        *(uint32_t*)&cb[(size_t)row1*DD + col] = pack_bf16x2(oacc[j][2]*i1, oacc[j][3]*i1);
    }
    if (tg == 0){
        lu_out[bh*SS + row0] = lu0;
        lu_out[bh*SS + row1] = lu1;
    }
}

// =====================================================================
// out2 DIRECT: block (mt, nc, b) owns out2[b][mt*128..][nc*128..].
// =====================================================================
__global__ void __launch_bounds__(256)
out2_direct(const bf16* __restrict__ Q, const bf16* __restrict__ K,
            const float* __restrict__ lu, float* __restrict__ out2)
{
    extern __shared__ bf16 o2sm[];
    bf16* Qs = o2sm;                // [2][128*FST]
    bf16* Ks = o2sm + 2*128*FST;    // [2][128*FST]

    const int tid = threadIdx.x;
    const int lane = tid & 31, g = lane >> 2, tg = lane & 3;
    const int w = tid >> 5;
    const int mt = blockIdx.x, nc = blockIdx.y, b = blockIdx.z;
    const int m0 = mt*128, n0 = nc*128;

    auto loadQK = [&](int buf, int hi){
        const bf16* qsrc = Q + ((size_t)(b*NH + hi) << 16) + (size_t)m0*DKH;
        const bf16* ksrc = K + ((size_t)(b*NH + hi) << 16) + (size_t)n0*DKH;
        #pragma unroll
        for (int i = 0; i < 4; i++){
            int id = tid + (i << 8);
            int r = id >> 3, c8 = (id & 7) << 3;
            cpasync16(smem_u32(&Qs[buf*128*FST + r*FST + c8]), qsrc + (size_t)r*DKH + c8);
            cpasync16(smem_u32(&Ks[buf*128*FST + r*FST + c8]), ksrc + (size_t)r*DKH + c8);
        }
    };
    loadQK(0, 0);
    asm volatile("cp.async.commit_group;\n");

    float acc[2][8][4];
    #pragma unroll
    for (int h2=0;h2<2;h2++)
        #pragma unroll
        for (int j=0;j<8;j++)
            #pragma unroll
            for (int v=0;v<4;v++) acc[h2][j][v]=0.f;

    const int row0 = m0 + w*16 + g, row1 = row0 + 8;

    for (int hi = 0; hi < NH; hi++){
        int buf = hi & 1;
        if (hi + 1 < NH){
            loadQK(buf^1, hi+1);
            asm volatile("cp.async.commit_group;\n");
            asm volatile("cp.async.wait_group 1;\n");
        } else {
            asm volatile("cp.async.wait_group 0;\n");
        }
        __syncthreads();

        float li0 = 1.0f / lu[(b*NH + hi)*SS + row0];
        float li1 = 1.0f / lu[(b*NH + hi)*SS + row1];

        uint32_t qf[4][4];
        const bf16* qb = Qs + buf*128*FST;
        #pragma unroll
        for (int kk = 0; kk < 4; kk++){
            const bf16* ap = &qb[(w*16 + g)*FST + kk*16 + 2*tg];
            qf[kk][0] = *(const uint32_t*)(ap);
            qf[kk][1] = *(const uint32_t*)(ap + 8*FST);
            qf[kk][2] = *(const uint32_t*)(ap + 8);
            qf[kk][3] = *(const uint32_t*)(ap + 8*FST + 8);
        }

        const bf16* Kc = Ks + buf*128*FST;
        #pragma unroll
        for (int half = 0; half < 2; half++){
            float sacc[8][4];
            #pragma unroll
            for (int j=0;j<8;j++)
                #pragma unroll
                for (int v=0;v<4;v++) sacc[j][v]=0.f;

            #pragma unroll
            for (int kk = 0; kk < 4; kk++){
                #pragma unroll
                for (int j = 0; j < 8; j++){
                    const bf16* bp = &Kc[(half*64 + j*8 + g)*FST + kk*16 + 2*tg];
                    uint32_t bfr[2] = { *(const uint32_t*)(bp), *(const uint32_t*)(bp + 8) };
                    mma_bf16(sacc[j], qf[kk], bfr);
                }
            }
            #pragma unroll
            for (int j = 0; j < 8; j++){
                acc[half][j][0] += __expf(sacc[j][0]-SHF)*li0;
                acc[half][j][1] += __expf(sacc[j][1]-SHF)*li0;
                acc[half][j][2] += __expf(sacc[j][2]-SHF)*li1;
                acc[half][j][3] += __expf(sacc[j][3]-SHF)*li1;
            }
        }
        __syncthreads();
    }

    const float k16 = 1.0f/16.0f;
    float* ob = out2 + ((size_t)b << 20);
    #pragma unroll
    for (int half = 0; half < 2; half++){
        #pragma unroll
        for (int j = 0; j < 8; j++){
            int col = n0 + half*64 + j*8 + 2*tg;
            *(float2*)&ob[(size_t)row0*SS + col] =
                make_float2(acc[half][j][0]*k16, acc[half][j][1]*k16);
            *(float2*)&ob[(size_t)row1*SS + col] =
                make_float2(acc[half][j][2]*k16, acc[half][j][3]*k16);
        }
    }
}

// ---------------- LayerNorm --------------------------------------------------
__global__ void __launch_bounds__(256)
layernorm(const float* __restrict__ R, const float* __restrict__ gamma,
          const float* __restrict__ beta, float* __restrict__ out)
{
    __shared__ float red[8];
    int row = blockIdx.x;
    int tid = threadIdx.x;
    const float* src = R + ((size_t)row << 10);
    float v[4];
    #pragma unroll
    for (int j=0;j<4;j++) v[j] = src[tid + (j<<8)];
    float s = v[0]+v[1]+v[2]+v[3];
    s = blockSum(s, red);
    float mu = s * (1.0f/1024.0f);
    float q = 0.f;
    #pragma unroll
    for (int j=0;j<4;j++) { float d = v[j]-mu; q += d*d; }
    q = blockSum(q, red);
    float inv = rsqrtf(q * (1.0f/1024.0f) + 1e-5f);
    #pragma unroll
    for (int j=0;j<4;j++) {
        int c = tid + (j<<8);
        out[((size_t)row << 10) + c] = (v[j]-mu)*inv*gamma[c] + beta[c];
    }
}

// ---------------- launch -----------------------------------------------------
extern "C" void kernel_launch(void* const* d_in, const int* in_sizes, int n_in,
                              void* d_out, int out_size)
{
    const float* x  = (const float*)d_in[0];
    const int*   ts = (const int*)  d_in[1];
    const float* Wq = (const float*)d_in[2];
    const float* bq = (const float*)d_in[3];
    const float* Wk = (const float*)d_in[4];
    const float* bk = (const float*)d_in[5];
    const float* Wv = (const float*)d_in[6];
    const float* bv = (const float*)d_in[7];
    const float* Wo = (const float*)d_in[8];
    const float* bo = (const float*)d_in[9];
    const float* ga = (const float*)d_in[10];
    const float* be = (const float*)d_in[11];

    float* out1 = (float*)d_out;
    float* out2 = out1 + (size_t)BB*SS*DD;

    void *pxb, *pwq, *pwk, *pwv, *pwo, *pq, *pk, *pv, *pvt, *plu, *pctxb, *pres;
    cudaGetSymbolAddress(&pxb, g_xb);
    cudaGetSymbolAddress(&pwq, g_wqb);
    cudaGetSymbolAddress(&pwk, g_wkb);
    cudaGetSymbolAddress(&pwv, g_wvb);
    cudaGetSymbolAddress(&pwo, g_wob);
    cudaGetSymbolAddress(&pq,  g_q);
    cudaGetSymbolAddress(&pk,  g_k);
    cudaGetSymbolAddress(&pv,  g_v);
    cudaGetSymbolAddress(&pvt, g_vt);
    cudaGetSymbolAddress(&plu, g_lu);
    cudaGetSymbolAddress(&pctxb, g_ctxb);
    cudaGetSymbolAddress(&pres,g_res);

    const int SM_FLSH = (128 + 2*64 + 2*64)*FST*2;        // 55296 B
    const int SM_O2   = 4*128*FST*2;                      // 73728 B
    cudaFuncSetAttribute((const void*)flash_pv,    cudaFuncAttributeMaxDynamicSharedMemorySize, SM_FLSH);
    cudaFuncSetAttribute((const void*)out2_direct, cudaFuncAttributeMaxDynamicSharedMemorySize, SM_O2);

    // fused bf16 conversion: x + 4 weight matrices, one launch
    to_bf16_all<<<8192, 256>>>(x, Wq, Wk, Wv, Wo,
                               (bf16*)pxb, (bf16*)pwq, (bf16*)pwk, (bf16*)pwv, (bf16*)pwo);

    // QKV projections (bf16 MMA) -> bf16 head layout
    gemm_bf16<0><<<dim3(24,32), 128>>>((const bf16*)pxb,
                                       (const bf16*)pwq, (const bf16*)pwk, (const bf16*)pwv,
                                       bq, bk, bv, nullptr,
                                       pq, pk, pv);

    // V transpose
    v_transpose<<<dim3(16,BHN), 256>>>((const bf16*)pv, (bf16*)pvt);

    // Flash attention: ctx (bf16) + unbiased row sums
    flash_pv<<<dim3(8,BHN), 256, SM_FLSH>>>((const bf16*)pq, (const bf16*)pk,
                                            (const bf16*)pvt, (bf16*)pctxb,
                                            (float*)plu, ts);

    // out2 computed directly
    out2_direct<<<dim3(8,8,BB), 256, SM_O2>>>((const bf16*)pq, (const bf16*)pk,
                                              (const float*)plu, out2);

    // out projection (bf16 MMA) + bias + residual -> fp32 res
    gemm_bf16<1><<<dim3(8,32), 128>>>((const bf16*)pctxb,
                                      (const bf16*)pwo, nullptr, nullptr,
                                      bo, nullptr, nullptr, x,
                                      pres, nullptr, nullptr);

    // LayerNorm -> output 1
    layernorm<<<dim3(BB*SS), 256>>>((const float*)pres, ga, be, out1);
}

// round 12
// speedup vs baseline: 1.5816x; 1.0577x over previous
#include <cuda_runtime.h>
#include <cuda_bf16.h>
#include <cstdint>
#include <math.h>

#define BB 4
#define SS 1024
#define DD 1024
#define NH 16
#define DKH 64
#define BHN (BB*NH)   // 64
#define FST 72        // smem stride (bf16) for 64-wide tiles
#define SHF 4.0f      // constant softmax shift (cancels exactly in normalization)

typedef __nv_bfloat16 bf16;

// ---------------- device scratch ----------------
__device__ bf16  g_xb[BB*SS*DD];          // x in bf16
__device__ bf16  g_wqb[DD*DD], g_wkb[DD*DD], g_wvb[DD*DD], g_wob[DD*DD];
__device__ bf16  g_q[BB*NH*SS*DKH];       // [b,h,s,dk], q pre-scaled 0.125
__device__ bf16  g_k[BB*NH*SS*DKH];
__device__ bf16  g_v[BB*NH*SS*DKH];
__device__ bf16  g_vt[BB*NH*DKH*SS];      // V transposed per head: [bh][dk][s]
__device__ float g_lu[BHN*SS];            // unbiased row sums (shifted)
__device__ bf16  g_ctxb[BB*SS*DD];        // ctx in bf16
__device__ float g_res[BB*SS*DD];

// ---------------- helpers ----------------
__device__ __forceinline__ float warpSumT(float v){
    #pragma unroll
    for (int o=16;o;o>>=1) v += __shfl_xor_sync(0xffffffffu, v, o);
    return v;
}
__device__ __forceinline__ float blockSum(float v, float* sh){
    v = warpSumT(v);
    int w = threadIdx.x >> 5, l = threadIdx.x & 31;
    if (l == 0) sh[w] = v;
    __syncthreads();
    float r = sh[0];
    #pragma unroll
    for (int i=1;i<8;i++) r += sh[i];
    __syncthreads();
    return r;
}
__device__ __forceinline__ void mma_bf16(float* d, const uint32_t* a, const uint32_t* b){
    asm volatile(
        "mma.sync.aligned.m16n8k16.row.col.f32.bf16.bf16.f32 "
        "{%0,%1,%2,%3}, {%4,%5,%6,%7}, {%8,%9}, {%0,%1,%2,%3};\n"
        : "+f"(d[0]), "+f"(d[1]), "+f"(d[2]), "+f"(d[3])
        : "r"(a[0]), "r"(a[1]), "r"(a[2]), "r"(a[3]),
          "r"(b[0]), "r"(b[1]));
}
__device__ __forceinline__ void cpasync16(uint32_t s, const void* g){
    asm volatile("cp.async.cg.shared.global [%0], [%1], 16;\n" :: "r"(s), "l"(g));
}
__device__ __forceinline__ uint32_t smem_u32(const void* p){
    return (uint32_t)__cvta_generic_to_shared(p);
}
__device__ __forceinline__ uint32_t pack_bf16x2(float x, float y){
    __nv_bfloat162 a = __floats2bfloat162_rn(x, y);
    return *reinterpret_cast<uint32_t*>(&a);
}

// ---------------- fused fp32 -> bf16 convert for all 5 tensors ------------
__global__ void __launch_bounds__(256)
to_bf16_all(const float* __restrict__ x,
            const float* __restrict__ Wq, const float* __restrict__ Wk,
            const float* __restrict__ Wv, const float* __restrict__ Wo,
            bf16* __restrict__ xb, bf16* __restrict__ wqb, bf16* __restrict__ wkb,
            bf16* __restrict__ wvb, bf16* __restrict__ wob)
{
    int bidx = blockIdx.x;
    const float* src; bf16* dst; int base;
    if      (bidx < 4096){ src = x;  dst = xb;  base = bidx; }
    else if (bidx < 5120){ src = Wq; dst = wqb; base = bidx - 4096; }
    else if (bidx < 6144){ src = Wk; dst = wkb; base = bidx - 5120; }
    else if (bidx < 7168){ src = Wv; dst = wvb; base = bidx - 6144; }
    else                 { src = Wo; dst = wob; base = bidx - 7168; }
    int i = (base*256 + threadIdx.x)*4;
    float4 v = *(const float4*)(src + i);
    uint2 u;
    u.x = pack_bf16x2(v.x, v.y);
    u.y = pack_bf16x2(v.z, v.w);
    *(uint2*)(dst + i) = u;
}

// =====================================================================
// bf16 GEMM core (m16n8k16), NT. 128 threads, 128x128 tiles.
//  MODE 0: QKV merged -> bf16 head-layout + (acc+bias)*scale
//  MODE 1: out-projection -> fp32 + bias + residual
// =====================================================================
template<int MODE>
__global__ void __launch_bounds__(128)
gemm_bf16(const bf16* __restrict__ A,
          const bf16* __restrict__ W0, const bf16* __restrict__ W1, const bf16* __restrict__ W2,
          const float* __restrict__ b0, const float* __restrict__ b1, const float* __restrict__ b2,
          const float* __restrict__ resid,
          void* __restrict__ o0, void* __restrict__ o1, void* __restrict__ o2)
{
    constexpr int BK=32, SB=40;
    constexpr int MT=4, NTL=8;
    constexpr int Kd=1024;

    __shared__ bf16 As[2][128*SB];
    __shared__ bf16 Bs[2][128*SB];

    const int tid = threadIdx.x;
    const int wsel = (MODE == 0) ? (blockIdx.x >> 3) : 0;
    const int bm0 = blockIdx.y*128;
    const int bn0 = (MODE == 0) ? (blockIdx.x & 7)*128 : blockIdx.x*128;

    const bf16* Bg    = (wsel==0) ? W0 : (wsel==1) ? W1 : W2;
    const float* bias = (wsel==0) ? b0 : (wsel==1) ? b1 : b2;
    void* C           = (wsel==0) ? o0 : (wsel==1) ? o1 : o2;
    const float scale = (MODE==0 && wsel==0) ? 0.125f : 1.0f;

    auto loadA = [&](int buf, int k0){
        #pragma unroll
        for (int i = 0; i < 4; i++){
            int id = tid + i*128;
            int r = id >> 2, c8 = (id & 3)*8;
            cpasync16(smem_u32(&As[buf][r*SB + c8]),
                      A + (size_t)(bm0 + r)*Kd + k0 + c8);
        }
    };
    auto loadB = [&](int buf, int k0){
        #pragma unroll
        for (int i = 0; i < 4; i++){
            int id = tid + i*128;
            int r = id >> 2, c8 = (id & 3)*8;
            cpasync16(smem_u32(&Bs[buf][r*SB + c8]),
                      Bg + (size_t)(bn0 + r)*Kd + k0 + c8);
        }
    };

    const int lane = tid & 31, g = lane >> 2, tg = lane & 3;
    const int warp = tid >> 5;
    const int wm = (warp >> 1) * 64, wn = (warp & 1) * 64;

    float acc[MT][NTL][4];
    #pragma unroll
    for (int i=0;i<MT;i++)
        #pragma unroll
        for (int j=0;j<NTL;j++)
            #pragma unroll
            for (int r=0;r<4;r++) acc[i][j][r] = 0.f;

    loadA(0, 0); loadB(0, 0);
    asm volatile("cp.async.commit_group;\n");

    for (int it = 0; it < Kd/BK; it++){
        int buf = it & 1;
        if (it + 1 < Kd/BK) {
            loadA(buf^1, (it+1)*BK); loadB(buf^1, (it+1)*BK);
            asm volatile("cp.async.commit_group;\n");
            asm volatile("cp.async.wait_group 1;\n");
        } else {
            asm volatile("cp.async.wait_group 0;\n");
        }
        __syncthreads();

        #pragma unroll
        for (int kk = 0; kk < 2; kk++){
            uint32_t af[MT][4], bfr[NTL][2];
            #pragma unroll
            for (int i = 0; i < MT; i++){
                const bf16* ap = &As[buf][(wm + i*16 + g)*SB + kk*16 + 2*tg];
                af[i][0] = *(const uint32_t*)(ap);
                af[i][1] = *(const uint32_t*)(ap + 8*SB);
                af[i][2] = *(const uint32_t*)(ap + 8);
                af[i][3] = *(const uint32_t*)(ap + 8*SB + 8);
            }
            #pragma unroll
            for (int j = 0; j < NTL; j++){
                const bf16* bp = &Bs[buf][(wn + j*8 + g)*SB + kk*16 + 2*tg];
                bfr[j][0] = *(const uint32_t*)(bp);
                bfr[j][1] = *(const uint32_t*)(bp + 8);
            }
            #pragma unroll
            for (int i = 0; i < MT; i++)
                #pragma unroll
                for (int j = 0; j < NTL; j++)
                    mma_bf16(acc[i][j], af[i], bfr[j]);
        }
        __syncthreads();
    }

    #pragma unroll
    for (int i = 0; i < MT; i++){
        #pragma unroll
        for (int rr = 0; rr < 2; rr++){
            int row = bm0 + wm + i*16 + g + rr*8;
            #pragma unroll
            for (int j = 0; j < NTL; j++){
                int col = bn0 + wn + j*8 + 2*tg;
                float vx = acc[i][j][rr*2+0] + bias[col];
                float vy = acc[i][j][rr*2+1] + bias[col+1];
                if (MODE == 0){
                    vx *= scale; vy *= scale;
                    int b = row >> 10, s = row & 1023;
                    int h = col >> 6, dd = col & 63;
                    uint32_t u = pack_bf16x2(vx, vy);
                    *(uint32_t*)&((bf16*)C)[((size_t)(b*NH + h) << 16) + s*DKH + dd] = u;
                } else {
                    size_t idx = (size_t)row*DD + col;
                    float2 r2 = *(const float2*)&resid[idx];
                    float2 o = make_float2(vx + r2.x, vy + r2.y);
                    *(float2*)&((float*)C)[idx] = o;
                }
            }
        }
    }
}

// =====================================================================
// V transpose per head: g_v[bh][s][dk] -> g_vt[bh][dk][s]
// =====================================================================
__global__ void __launch_bounds__(256)
v_transpose(const bf16* __restrict__ V, bf16* __restrict__ Vt)
{
    __shared__ bf16 t[64][FST];
    const int sc = blockIdx.x, bh = blockIdx.y;
    const int tid = threadIdx.x;
    const bf16* src = V + ((size_t)bh << 16) + sc*64*DKH;

    #pragma unroll
    for (int i = 0; i < 2; i++){
        int id = tid + (i << 8);
        int r = id >> 3, c8 = (id & 7) << 3;
        *(uint4*)&t[r][c8] = *(const uint4*)(src + r*DKH + c8);
    }
    __syncthreads();

    bf16* dst = Vt + ((size_t)bh << 16) + sc*64;
    #pragma unroll
    for (int i = 0; i < 2; i++){
        int id = tid + (i << 8);
        int r = id >> 3, c8 = (id & 7) << 3;
        union { uint4 u; bf16 h[8]; } o;
        #pragma unroll
        for (int tj = 0; tj < 8; tj++) o.h[tj] = t[c8 + tj][r];
        *(uint4*)(dst + (size_t)r*SS + c8) = o.u;
    }
}

// =====================================================================
// FLASH: per (mtile=128, bh). S in regs, constant-shift softmax, P@V.
// ctx written in bf16. __launch_bounds__(256,2): cap regs at 128 for
// 2 blocks/SM; exp->pack->PV interleaved per kk to shrink live set.
// =====================================================================
__global__ void __launch_bounds__(256, 2)
flash_pv(const bf16* __restrict__ Q, const bf16* __restrict__ K,
         const bf16* __restrict__ Vt, bf16* __restrict__ ctx,
         float* __restrict__ lu_out, const int* __restrict__ ts_ptr)
{
    extern __shared__ bf16 fsm[];
    bf16* Qs = fsm;                       // 128*FST
    bf16* Ks = fsm + 128*FST;             // 2*64*FST
    bf16* Vs = fsm + 128*FST + 2*64*FST;  // 2*64*FST

    const int tid = threadIdx.x;
    const int lane = tid & 31, g = lane >> 2, tg = lane & 3;
    const int w = tid >> 5;
    const int mt = blockIdx.x, bh = blockIdx.y;
    const int m0 = mt*128;

    const bf16* Qb = Q  + ((size_t)bh << 16) + (size_t)m0*DKH;
    const bf16* Kb = K  + ((size_t)bh << 16);
    const bf16* Vb = Vt + ((size_t)bh << 16);

    #pragma unroll
    for (int i = 0; i < 4; i++){
        int id = tid + (i << 8);
        int r = id >> 3, c8 = (id & 7) << 3;
        cpasync16(smem_u32(&Qs[r*FST + c8]), Qb + r*DKH + c8);
    }
    auto loadK = [&](int buf, int k0){
        #pragma unroll
        for (int i = 0; i < 2; i++){
            int id = tid + (i << 8);
            int r = id >> 3, c8 = (id & 7) << 3;
            cpasync16(smem_u32(&Ks[buf*64*FST + r*FST + c8]),
                      Kb + (size_t)(k0 + r)*DKH + c8);
        }
    };
    auto loadV = [&](int buf, int k0){
        #pragma unroll
        for (int i = 0; i < 2; i++){
            int id = tid + (i << 8);
            int r = id >> 3, c8 = (id & 7) << 3;
            cpasync16(smem_u32(&Vs[buf*64*FST + r*FST + c8]),
                      Vb + (size_t)r*SS + k0 + c8);
        }
    };
    loadK(0, 0); loadV(0, 0);
    asm volatile("cp.async.commit_group;\n");

    float oacc[8][4];
    #pragma unroll
    for (int j=0;j<8;j++)
        #pragma unroll
        for (int v=0;v<4;v++) oacc[j][v]=0.f;
    float l0=0.f, l1=0.f, lu0=0.f, lu1=0.f;

    const bool dob = (ts_ptr[0] < 8) && (mt == 0) && (w < 4);
    const int row0 = m0 + w*16 + g, row1 = row0 + 8;

    uint32_t qf[4][4];
    bool qldd = false;

    for (int c = 0; c < 16; c++){
        int buf = c & 1;
        if (c + 1 < 16){
            loadK(buf^1, (c+1)*64); loadV(buf^1, (c+1)*64);
            asm volatile("cp.async.commit_group;\n");
            asm volatile("cp.async.wait_group 1;\n");
        } else {
            asm volatile("cp.async.wait_group 0;\n");
        }
        __syncthreads();

        if (!qldd){
            #pragma unroll
            for (int kk = 0; kk < 4; kk++){
                const bf16* ap = &Qs[(w*16 + g)*FST + kk*16 + 2*tg];
                qf[kk][0] = *(const uint32_t*)(ap);
                qf[kk][1] = *(const uint32_t*)(ap + 8*FST);
                qf[kk][2] = *(const uint32_t*)(ap + 8);
                qf[kk][3] = *(const uint32_t*)(ap + 8*FST + 8);
            }
            qldd = true;
        }

        const bf16* Kc = Ks + buf*64*FST;
        const bf16* Vc = Vs + buf*64*FST;

        float sacc[8][4];
        #pragma unroll
        for (int j=0;j<8;j++)
            #pragma unroll
            for (int v=0;v<4;v++) sacc[j][v]=0.f;

        #pragma unroll
        for (int kk = 0; kk < 4; kk++){
            #pragma unroll
            for (int j = 0; j < 8; j++){
                const bf16* bp = &Kc[(j*8 + g)*FST + kk*16 + 2*tg];
                uint32_t bfr[2] = { *(const uint32_t*)(bp), *(const uint32_t*)(bp + 8) };
                mma_bf16(sacc[j], qf[kk], bfr);
            }
        }

        const bool bchunk = dob && (c == 0);
        if (bchunk){
            float u0=0.f, u1=0.f;
            #pragma unroll
            for (int j = 0; j < 8; j++){
                u0 += __expf(sacc[j][0]-SHF) + __expf(sacc[j][1]-SHF);
                u1 += __expf(sacc[j][2]-SHF) + __expf(sacc[j][3]-SHF);
            }
            lu0 += u0; lu1 += u1;
            #pragma unroll
            for (int j = 0; j < 8; j++){
                int col = j*8 + 2*tg;
                sacc[j][0] += 0.1f / (fabsf((float)(row0 - col))     + 1.0f);
                sacc[j][1] += 0.1f / (fabsf((float)(row0 - col - 1)) + 1.0f);
                sacc[j][2] += 0.1f / (fabsf((float)(row1 - col))     + 1.0f);
                sacc[j][3] += 0.1f / (fabsf((float)(row1 - col - 1)) + 1.0f);
            }
        }

        // exp -> pack -> PV MMA interleaved per kk (pk arrays eliminated)
        float r0 = 0.f, r1 = 0.f;
        #pragma unroll
        for (int kk = 0; kk < 4; kk++){
            const int j0 = 2*kk, j1 = 2*kk + 1;
            float p00 = __expf(sacc[j0][0]-SHF), p01 = __expf(sacc[j0][1]-SHF);
            float p02 = __expf(sacc[j0][2]-SHF), p03 = __expf(sacc[j0][3]-SHF);
            float p10 = __expf(sacc[j1][0]-SHF), p11 = __expf(sacc[j1][1]-SHF);
            float p12 = __expf(sacc[j1][2]-SHF), p13 = __expf(sacc[j1][3]-SHF);
            r0 += p00 + p01 + p10 + p11;
            r1 += p02 + p03 + p12 + p13;
            uint32_t a[4];
            a[0] = pack_bf16x2(p00, p01);
            a[1] = pack_bf16x2(p02, p03);
            a[2] = pack_bf16x2(p10, p11);
            a[3] = pack_bf16x2(p12, p13);
            #pragma unroll
            for (int j = 0; j < 8; j++){
                const bf16* bp = &Vc[(j*8 + g)*FST + kk*16 + 2*tg];
                uint32_t b2[2] = { *(const uint32_t*)(bp), *(const uint32_t*)(bp + 8) };
                mma_bf16(oacc[j], a, b2);
            }
        }
        l0 += r0; l1 += r1;
        if (!bchunk){ lu0 += r0; lu1 += r1; }
        __syncthreads();
    }

    #pragma unroll
    for (int o = 1; o < 4; o <<= 1){
        l0  += __shfl_xor_sync(0xffffffffu, l0,  o);
        l1  += __shfl_xor_sync(0xffffffffu, l1,  o);
        lu0 += __shfl_xor_sync(0xffffffffu, lu0, o);
        lu1 += __shfl_xor_sync(0xffffffffu, lu1, o);
    }
    float i0 = 1.0f / l0, i1 = 1.0f / l1;

    bf16* cb = ctx + ((size_t)(bh >> 4) << 20) + (size_t)(bh & 15)*64;
    #pragma unroll
    for (int j = 0; j < 8; j++){
        int col = j*8 + 2*tg;
        *(uint32_t*)&cb[(size_t)row0*DD + col] = pack_bf16x2(oacc[j][0]*i0, oacc[j][1]*i0);
        *(uint32_t*)&cb[(size_t)row1*DD + col] = pack_bf16x2(oacc[j][2]*i1, oacc[j][3]*i1);
    }
    if (tg == 0){
        lu_out[bh*SS + row0] = lu0;
        lu_out[bh*SS + row1] = lu1;
    }
}

// =====================================================================
// out2 DIRECT: block (mt, nc, b) owns out2[b][mt*128..][nc*128..].
// =====================================================================
__global__ void __launch_bounds__(256, 2)
out2_direct(const bf16* __restrict__ Q, const bf16* __restrict__ K,
            const float* __restrict__ lu, float* __restrict__ out2)
{
    extern __shared__ bf16 o2sm[];
    bf16* Qs = o2sm;                // [2][128*FST]
    bf16* Ks = o2sm + 2*128*FST;    // [2][128*FST]

    const int tid = threadIdx.x;
    const int lane = tid & 31, g = lane >> 2, tg = lane & 3;
    const int w = tid >> 5;
    const int mt = blockIdx.x, nc = blockIdx.y, b = blockIdx.z;
    const int m0 = mt*128, n0 = nc*128;

    auto loadQK = [&](int buf, int hi){
        const bf16* qsrc = Q + ((size_t)(b*NH + hi) << 16) + (size_t)m0*DKH;
        const bf16* ksrc = K + ((size_t)(b*NH + hi) << 16) + (size_t)n0*DKH;
        #pragma unroll
        for (int i = 0; i < 4; i++){
            int id = tid + (i << 8);
            int r = id >> 3, c8 = (id & 7) << 3;
            cpasync16(smem_u32(&Qs[buf*128*FST + r*FST + c8]), qsrc + (size_t)r*DKH + c8);
            cpasync16(smem_u32(&Ks[buf*128*FST + r*FST + c8]), ksrc + (size_t)r*DKH + c8);
        }
    };
    loadQK(0, 0);
    asm volatile("cp.async.commit_group;\n");

    float acc[2][8][4];
    #pragma unroll
    for (int h2=0;h2<2;h2++)
        #pragma unroll
        for (int j=0;j<8;j++)
            #pragma unroll
            for (int v=0;v<4;v++) acc[h2][j][v]=0.f;

    const int row0 = m0 + w*16 + g, row1 = row0 + 8;

    for (int hi = 0; hi < NH; hi++){
        int buf = hi & 1;
        if (hi + 1 < NH){
            loadQK(buf^1, hi+1);
            asm volatile("cp.async.commit_group;\n");
            asm volatile("cp.async.wait_group 1;\n");
        } else {
            asm volatile("cp.async.wait_group 0;\n");
        }
        __syncthreads();

        float li0 = 1.0f / lu[(b*NH + hi)*SS + row0];
        float li1 = 1.0f / lu[(b*NH + hi)*SS + row1];

        uint32_t qf[4][4];
        const bf16* qb = Qs + buf*128*FST;
        #pragma unroll
        for (int kk = 0; kk < 4; kk++){
            const bf16* ap = &qb[(w*16 + g)*FST + kk*16 + 2*tg];
            qf[kk][0] = *(const uint32_t*)(ap);
            qf[kk][1] = *(const uint32_t*)(ap + 8*FST);
            qf[kk][2] = *(const uint32_t*)(ap + 8);
            qf[kk][3] = *(const uint32_t*)(ap + 8*FST + 8);
        }

        const bf16* Kc = Ks + buf*128*FST;
        #pragma unroll
        for (int half = 0; half < 2; half++){
            float sacc[8][4];
            #pragma unroll
            for (int j=0;j<8;j++)
                #pragma unroll
                for (int v=0;v<4;v++) sacc[j][v]=0.f;

            #pragma unroll
            for (int kk = 0; kk < 4; kk++){
                #pragma unroll
                for (int j = 0; j < 8; j++){
                    const bf16* bp = &Kc[(half*64 + j*8 + g)*FST + kk*16 + 2*tg];
                    uint32_t bfr[2] = { *(const uint32_t*)(bp), *(const uint32_t*)(bp + 8) };
                    mma_bf16(sacc[j], qf[kk], bfr);
                }
            }
            #pragma unroll
            for (int j = 0; j < 8; j++){
                acc[half][j][0] += __expf(sacc[j][0]-SHF)*li0;
                acc[half][j][1] += __expf(sacc[j][1]-SHF)*li0;
                acc[half][j][2] += __expf(sacc[j][2]-SHF)*li1;
                acc[half][j][3] += __expf(sacc[j][3]-SHF)*li1;
            }
        }
        __syncthreads();
    }

    const float k16 = 1.0f/16.0f;
    float* ob = out2 + ((size_t)b << 20);
    #pragma unroll
    for (int half = 0; half < 2; half++){
        #pragma unroll
        for (int j = 0; j < 8; j++){
            int col = n0 + half*64 + j*8 + 2*tg;
            *(float2*)&ob[(size_t)row0*SS + col] =
                make_float2(acc[half][j][0]*k16, acc[half][j][1]*k16);
            *(float2*)&ob[(size_t)row1*SS + col] =
                make_float2(acc[half][j][2]*k16, acc[half][j][3]*k16);
        }
    }
}

// ---------------- LayerNorm --------------------------------------------------
__global__ void __launch_bounds__(256)
layernorm(const float* __restrict__ R, const float* __restrict__ gamma,
          const float* __restrict__ beta, float* __restrict__ out)
{
    __shared__ float red[8];
    int row = blockIdx.x;
    int tid = threadIdx.x;
    const float* src = R + ((size_t)row << 10);
    float v[4];
    #pragma unroll
    for (int j=0;j<4;j++) v[j] = src[tid + (j<<8)];
    float s = v[0]+v[1]+v[2]+v[3];
    s = blockSum(s, red);
    float mu = s * (1.0f/1024.0f);
    float q = 0.f;
    #pragma unroll
    for (int j=0;j<4;j++) { float d = v[j]-mu; q += d*d; }
    q = blockSum(q, red);
    float inv = rsqrtf(q * (1.0f/1024.0f) + 1e-5f);
    #pragma unroll
    for (int j=0;j<4;j++) {
        int c = tid + (j<<8);
        out[((size_t)row << 10) + c] = (v[j]-mu)*inv*gamma[c] + beta[c];
    }
}

// ---------------- launch -----------------------------------------------------
extern "C" void kernel_launch(void* const* d_in, const int* in_sizes, int n_in,
                              void* d_out, int out_size)
{
    const float* x  = (const float*)d_in[0];
    const int*   ts = (const int*)  d_in[1];
    const float* Wq = (const float*)d_in[2];
    const float* bq = (const float*)d_in[3];
    const float* Wk = (const float*)d_in[4];
    const float* bk = (const float*)d_in[5];
    const float* Wv = (const float*)d_in[6];
    const float* bv = (const float*)d_in[7];
    const float* Wo = (const float*)d_in[8];
    const float* bo = (const float*)d_in[9];
    const float* ga = (const float*)d_in[10];
    const float* be = (const float*)d_in[11];

    float* out1 = (float*)d_out;
    float* out2 = out1 + (size_t)BB*SS*DD;

    void *pxb, *pwq, *pwk, *pwv, *pwo, *pq, *pk, *pv, *pvt, *plu, *pctxb, *pres;
    cudaGetSymbolAddress(&pxb, g_xb);
    cudaGetSymbolAddress(&pwq, g_wqb);
    cudaGetSymbolAddress(&pwk, g_wkb);
    cudaGetSymbolAddress(&pwv, g_wvb);
    cudaGetSymbolAddress(&pwo, g_wob);
    cudaGetSymbolAddress(&pq,  g_q);
    cudaGetSymbolAddress(&pk,  g_k);
    cudaGetSymbolAddress(&pv,  g_v);
    cudaGetSymbolAddress(&pvt, g_vt);
    cudaGetSymbolAddress(&plu, g_lu);
    cudaGetSymbolAddress(&pctxb, g_ctxb);
    cudaGetSymbolAddress(&pres,g_res);

    const int SM_FLSH = (128 + 2*64 + 2*64)*FST*2;        // 55296 B
    const int SM_O2   = 4*128*FST*2;                      // 73728 B
    cudaFuncSetAttribute((const void*)flash_pv,    cudaFuncAttributeMaxDynamicSharedMemorySize, SM_FLSH);
    cudaFuncSetAttribute((const void*)out2_direct, cudaFuncAttributeMaxDynamicSharedMemorySize, SM_O2);

    // fused bf16 conversion: x + 4 weight matrices, one launch
    to_bf16_all<<<8192, 256>>>(x, Wq, Wk, Wv, Wo,
                               (bf16*)pxb, (bf16*)pwq, (bf16*)pwk, (bf16*)pwv, (bf16*)pwo);

    // QKV projections (bf16 MMA) -> bf16 head layout
    gemm_bf16<0><<<dim3(24,32), 128>>>((const bf16*)pxb,
                                       (const bf16*)pwq, (const bf16*)pwk, (const bf16*)pwv,
                                       bq, bk, bv, nullptr,
                                       pq, pk, pv);

    // V transpose
    v_transpose<<<dim3(16,BHN), 256>>>((const bf16*)pv, (bf16*)pvt);

    // Flash attention: ctx (bf16) + unbiased row sums
    flash_pv<<<dim3(8,BHN), 256, SM_FLSH>>>((const bf16*)pq, (const bf16*)pk,
                                            (const bf16*)pvt, (bf16*)pctxb,
                                            (float*)plu, ts);

    // out2 computed directly
    out2_direct<<<dim3(8,8,BB), 256, SM_O2>>>((const bf16*)pq, (const bf16*)pk,
                                              (const float*)plu, out2);

    // out projection (bf16 MMA) + bias + residual -> fp32 res
    gemm_bf16<1><<<dim3(8,32), 128>>>((const bf16*)pctxb,
                                      (const bf16*)pwo, nullptr, nullptr,
                                      bo, nullptr, nullptr, x,
                                      pres, nullptr, nullptr);

    // LayerNorm -> output 1
    layernorm<<<dim3(BB*SS), 256>>>((const float*)pres, ga, be, out1);
}